// round 12
// baseline (speedup 1.0000x reference)
#include <cuda_runtime.h>
#include <cuda_bf16.h>

// Problem constants (fixed by the reference setup).
#define BB   256
#define NN   4000
#define GG   50
#define M_TOT (BB * NN)      // 1,024,000 elements
#define TMAX  (BB * GG)      // 12,800 max TPs per threshold
#define NBKT  2048           // 11-bit value buckets (keeps hist smem <= 110.6KB -> 2 blocks/SM)
#define NW    125            // 32-bit words covering NN proposals (125*32 == 4000)

// ----------------------------------------------------------------------------
// Device scratch (static globals — zero-initialized at load; every counter is
// restored to zero by its consumer, so graph replays are deterministic)
// ----------------------------------------------------------------------------
__device__ unsigned long long g_list[2][TMAX];       // compacted TP keys (unordered)
__device__ unsigned long long g_btmp[2][TMAX];       // bucketed, unsorted-within-bucket
__device__ unsigned long long g_sorted[2][TMAX];     // fully sorted ascending keys
__device__ int g_T[2];                               // TP counts
__device__ __align__(16) int g_bcount[2][NBKT];      // bucket counts (filled by greedy)
__device__ int g_boff[2][NBKT + 1];                  // bucket offsets
__device__ int g_c[2][TMAX + 1];                     // lower-bound histogram
__device__ int g_done1;                              // greedy completion counter
__device__ int g_done2[2];                           // hist completion counters

// ----------------------------------------------------------------------------
// Key: ascending key == (conf descending, index ascending).
// Layout: [conf-ord 32][idx 20][bucket 12]; bucket (0..2047) monotone with key.
// ----------------------------------------------------------------------------
__device__ __forceinline__ unsigned int ford(float f) {
    unsigned int u = __float_as_uint(f);
    return (u & 0x80000000u) ? ~u : (u | 0x80000000u);   // ascending float order
}
__device__ __forceinline__ int bucket_of(float conf) {
    int bi = (int)(conf * 2048.0f);
    bi = bi < 0 ? 0 : (bi > 2047 ? 2047 : bi);
    return 2047 - bi;                                     // higher conf -> smaller bucket
}
__device__ __forceinline__ unsigned long long make_key(float conf, int idx) {
    unsigned int kh = ~ford(conf);                        // ascending kh == descending conf
    return ((unsigned long long)kh << 32)
         | ((unsigned long long)(unsigned int)idx << 12)
         | (unsigned long long)bucket_of(conf);
}

// ============================================================================
// K1: greedy matching + TP emission; the LAST block performs the full bucket
// sort for both thresholds. The sort reuses the dynamic pot[] region for its
// off/fill tables, so the kernel's SMEM footprint (and occupancy) is unchanged.
// ============================================================================
__global__ void __launch_bounds__(512) k_greedy(const float2* __restrict__ segs,
                                                const float2* __restrict__ gts,
                                                const float*  __restrict__ scores) {
    const int b = blockIdx.x, tid = threadIdx.x;
    const int lane = tid & 31, warp = tid >> 5;           // 16 warps
    extern __shared__ unsigned int pot[];                 // [2][GG][NW] dynamic (50,000 B)
    __shared__ float4 sgt[GG];                            // sorted: {x, y, len, idx-bits}
    __shared__ float2 raw[GG];
    __shared__ unsigned int suse[2][NW];
    __shared__ int s_tab[64];
    __shared__ int s_maxlen;                              // float bits (positive)
    __shared__ int s_cnt[2], s_base[2];
    __shared__ int s_wtot[16];
    __shared__ int s_islast;

    // zero bitmaps + zero this launch's g_c slice (distributed over 256 blocks)
    for (int i = tid; i < 2 * GG * NW; i += 512) pot[i] = 0u;
    for (int i = b * 512 + tid; i < 2 * (TMAX + 1); i += BB * 512) ((int*)g_c)[i] = 0;
    if (tid == 0) s_maxlen = 0;
    if (tid < 2) s_cnt[tid] = 0;
    if (tid < GG) raw[tid] = gts[b * GG + tid];
    __syncthreads();

    // sort gts by start (rank sort, stable on ties) + max length
    if (tid < GG) {
        float2 t = raw[tid];
        int r = 0;
        for (int j = 0; j < GG; ++j) {
            float xj = raw[j].x;
            r += (xj < t.x) || (xj == t.x && j < tid);
        }
        sgt[r] = make_float4(t.x, t.y, t.y - t.x, __int_as_float(tid));
        atomicMax(&s_maxlen, __float_as_int(t.y - t.x)); // positive floats: int cmp ok
    }
    __syncthreads();
    // 64-entry start table: s_tab[q] = first j with sgt[j].x >= q/64
    if (tid < 64) {
        float thr = (float)tid * (1.0f / 64.0f);
        int j = 0;
        while (j < GG && sgt[j].x < thr) ++j;
        s_tab[tid] = j;
    }
    __syncthreads();
    const float maxlg = __int_as_float(s_maxlen);

    // ---- candidate evaluation over the pruned gt window ----
    for (int n = tid; n < NN; n += 512) {
        float2 s = segs[b * NN + n];
        float la = s.y - s.x;
        float xlo = s.x - maxlg;
        int q = (int)(xlo * 64.0f) - 1;                   // -1: conservative vs fp round-up
        q = q < 0 ? 0 : (q > 63 ? 63 : q);
        int w = n >> 5;
        unsigned int wbit = 1u << (n & 31);
        for (int j = s_tab[q]; j < GG; ++j) {
            float4 t = sgt[j];                            // LDS.128
            if (t.x >= s.y) break;                        // inter <= 0 beyond here
            float inter = fminf(s.y, t.y) - fmaxf(s.x, t.x);
            float ssum  = la + t.z;                       // la + lg (> 0)
            int g = __float_as_int(t.w);
            // iou > 0.5 <=> 3*inter > la+lg ; iou > 0.75 <=> 7*inter > 3*(la+lg)
            if (3.0f * inter > ssum)         atomicOr(&pot[g * NW + w], wbit);
            if (7.0f * inter > 3.0f * ssum)  atomicOr(&pot[(GG + g) * NW + w], wbit);
        }
    }
    __syncthreads();

    // ---- greedy claims: one warp per threshold, used bits in registers ----
    if (warp < 2) {
        const int z = warp;
        unsigned int usedreg[4] = {0u, 0u, 0u, 0u};
        const unsigned int* P = pot + z * GG * NW;
        for (int g = 0; g < GG; ++g) {
            unsigned int best = 0xFFFFFFFFu;
#pragma unroll
            for (int s = 0; s < 4; ++s) {
                int w = s * 32 + lane;
                if (w < NW) {
                    unsigned int c = P[g * NW + w] & ~usedreg[s];
                    if (c) best = min(best, (unsigned int)(w * 32 + __ffs(c) - 1));
                }
            }
            unsigned int m = __reduce_min_sync(0xFFFFFFFFu, best);
            if (m != 0xFFFFFFFFu) {
                int wm = (int)(m >> 5);
                if ((wm & 31) == lane) usedreg[wm >> 5] |= 1u << (m & 31);
            }
        }
#pragma unroll
        for (int s = 0; s < 4; ++s) {
            int w = s * 32 + lane;
            if (w < NW) suse[z][w] = usedreg[s];
        }
    }
    __syncthreads();

    // ---- emit TP keys: block-aggregated reservation (1 global atomic per z) --
    int z = -1, w = 0, cnt = 0, lbase = 0;
    unsigned int word = 0;
    if (tid < 2 * NW) {
        z = tid / NW; w = tid % NW;
        word = suse[z][w];
        cnt = __popc(word);
        if (cnt) lbase = atomicAdd(&s_cnt[z], cnt);       // smem offsets
    }
    __syncthreads();
    if (tid < 2) s_base[tid] = s_cnt[tid] ? atomicAdd(&g_T[tid], s_cnt[tid]) : 0;
    __syncthreads();
    if (cnt) {
        int p = s_base[z] + lbase;
        while (word) {
            int bit = __ffs(word) - 1;
            word &= word - 1;
            int idx = b * NN + w * 32 + bit;
            unsigned long long key = make_key(scores[idx], idx);
            g_list[z][p++] = key;
            atomicAdd(&g_bcount[z][(int)(key & 0xFFFull)], 1);
        }
    }

    // ---- last-block election ----
    __threadfence();
    __syncthreads();
    if (tid == 0) s_islast = (atomicAdd(&g_done1, 1) == BB - 1);
    __syncthreads();
    if (!s_islast) return;

    // ======================= SORT PHASE (last block) ========================
    // Reuse the pot[] dynamic region: off[0..NBKT] at ints [0..2048],
    // fill[NBKT] at ints [2052..4099] (byte 8208, 16-aligned).
    int* s_off  = (int*)pot;
    int* s_fill = (int*)pot + 2052;

    for (int zz = 0; zz < 2; ++zz) {
        int T = __ldcg(&g_T[zz]);

        // load 4 consecutive bucket counts per thread, restore them to zero
        int4* bc = (int4*)&g_bcount[zz][0];               // rows are 8KB apart: 16-aligned
        int4 c4 = bc[tid];
        bc[tid] = make_int4(0, 0, 0, 0);
        ((int4*)s_fill)[tid] = make_int4(0, 0, 0, 0);

        // block-wide exclusive scan over 2048 bins (4 per thread, 16 warps)
        int loc[4]; int s = 0;
        loc[0] = s; s += c4.x; loc[1] = s; s += c4.y;
        loc[2] = s; s += c4.z; loc[3] = s; s += c4.w;
        int v = s;
#pragma unroll
        for (int d = 1; d < 32; d <<= 1) {
            int o = __shfl_up_sync(0xFFFFFFFFu, v, d);
            if (lane >= d) v += o;
        }
        if (lane == 31) s_wtot[warp] = v;
        __syncthreads();
        if (warp == 0) {
            int wv = (lane < 16) ? s_wtot[lane] : 0;
            int wi = wv;
#pragma unroll
            for (int d = 1; d < 32; d <<= 1) {
                int o = __shfl_up_sync(0xFFFFFFFFu, wi, d);
                if (lane >= d) wi += o;
            }
            if (lane < 16) s_wtot[lane] = wi - wv;
        }
        __syncthreads();
        int excl = s_wtot[warp] + (v - s);
        int base = tid * 4;
#pragma unroll
        for (int j = 0; j < 4; ++j) s_off[base + j] = excl + loc[j];
        if (tid == 511) s_off[NBKT] = excl + s;
        __syncthreads();

        // scatter keys into buckets (global staging buffer)
        for (int i = tid; i < T; i += 512) {
            unsigned long long k = __ldcg(&g_list[zz][i]);
            int bk = (int)(k & 0xFFFull);
            g_btmp[zz][s_off[bk] + atomicAdd(&s_fill[bk], 1)] = k;
        }
        __syncthreads();

        // thread-per-bucket rank sort (avg ~6 keys/bucket)
        for (int bk = tid; bk < NBKT; bk += 512) {
            int st = s_off[bk], en = s_off[bk + 1];
            for (int i = st; i < en; ++i) {
                unsigned long long k = g_btmp[zz][i];
                int r = 0;
                for (int j = st; j < en; ++j) r += (g_btmp[zz][j] < k) ? 1 : 0;
                g_sorted[zz][st + r] = k;
            }
        }
        for (int i = tid; i <= NBKT; i += 512) g_boff[zz][i] = s_off[i];
        __syncthreads();                                  // s_off/s_fill reused for zz=1
    }
    if (tid == 0) g_done1 = 0;                            // reset for next replay
}

// ============================================================================
// K2: lower-bound histogram (2048-way buckets, ~3 dependent LDS levels); the
// LAST block per threshold performs the full AP finalize, overlaying its
// working arrays onto the dynamic SMEM region.
// Dynamic layout (hist):  soff[0..2048] | sk[TMAX] (8B-aligned at int 2050)
// Dynamic layout (final): s_c[TMAX+1] | prec[TMAX] | s_suf[1024]
// ============================================================================
__global__ void __launch_bounds__(1024) k_hist(const float* __restrict__ scores,
                                               float* __restrict__ out) {
    const int z = blockIdx.y, tid = threadIdx.x;
    const int lane = tid & 31, warp = tid >> 5;
    extern __shared__ int sh[];
    int* soff = sh;                                       // NBKT+1
    unsigned long long* sk = (unsigned long long*)(sh + 2050); // byte 8200, 8-aligned
    __shared__ int s_last;
    __shared__ int    wsum[32];
    __shared__ float  wmax[32];
    __shared__ double wdbl[32];
    __shared__ float  s_gmax;

    int T = g_T[z];
    for (int i = tid; i < T; i += 1024) sk[i] = g_sorted[z][i];
    for (int i = tid; i <= NBKT; i += 1024) soff[i] = g_boff[z][i];
    __syncthreads();

    // ---- histogram: in-bucket lower bound == global lower bound ----
    int stride = gridDim.x * 1024;
    for (int idx = blockIdx.x * 1024 + tid; idx < M_TOT; idx += stride) {
        unsigned long long key = make_key(__ldg(&scores[idx]), idx);
        int bk = (int)(key & 0xFFFull);
        int lo = soff[bk], hi = soff[bk + 1];
        while (lo < hi) {
            int mid = (lo + hi) >> 1;
            if (sk[mid] < key) lo = mid + 1; else hi = mid;
        }
        atomicAdd(&g_c[z][lo], 1);
    }

    // ---- last-block election (per z) ----
    __threadfence();
    __syncthreads();
    if (tid == 0) s_last = (atomicAdd(&g_done2[z], 1) == (int)gridDim.x - 1);
    __syncthreads();
    if (!s_last) return;

    // ======================= FINALIZE (last block per z) ====================
    int*   s_c   = sh;                                    // TMAX+1 (+pad)
    float* prec  = (float*)(sh + TMAX + 4);               // TMAX
    float* s_suf = (float*)(sh + 2 * TMAX + 4);           // 1024

    if (T == 0) { if (tid == 0) { out[z] = 0.0f; g_T[z] = 0; g_done2[z] = 0; } return; }
    int bins = T + 1;

    __syncthreads();                                      // done with soff/sk
    for (int i = tid; i < bins; i += 1024) s_c[i] = g_c[z][i];  // coalesced stage
    __syncthreads();

    int CH = (bins + 1023) >> 10;
    int st = min(tid * CH, bins), en = min(st + CH, bins);

    // ---- block-wide exclusive prefix sum of per-thread bin sums ----
    int ssum = 0;
    for (int p = st; p < en; ++p) ssum += s_c[p];
    int v = ssum;
#pragma unroll
    for (int d = 1; d < 32; d <<= 1) {
        int o = __shfl_up_sync(0xFFFFFFFFu, v, d);
        if (lane >= d) v += o;
    }
    if (lane == 31) wsum[warp] = v;
    __syncthreads();
    if (warp == 0) {
        int w = wsum[lane], wi = w;
#pragma unroll
        for (int d = 1; d < 32; d <<= 1) {
            int o = __shfl_up_sync(0xFFFFFFFFu, wi, d);
            if (lane >= d) wi += o;
        }
        wsum[lane] = wi - w;
    }
    __syncthreads();
    int C = wsum[warp] + (v - ssum);

    // ---- precision values + chunk max ----
    float mx = 0.0f;
    for (int p = st; p < en; ++p) {
        C += s_c[p];
        if (p < T) {
            float pr = (float)(p + 1) / (float)C;
            prec[p] = pr;
            mx = fmaxf(mx, pr);
        }
    }

    // ---- exclusive suffix-max over chunks (reversed exclusive max-scan) ----
    s_suf[1023 - tid] = mx;
    __syncthreads();
    float a = s_suf[tid], ai = a;
#pragma unroll
    for (int d = 1; d < 32; d <<= 1) {
        float o = __shfl_up_sync(0xFFFFFFFFu, ai, d);
        if (lane >= d) ai = fmaxf(ai, o);
    }
    float le = __shfl_up_sync(0xFFFFFFFFu, ai, 1);
    if (lane == 0) le = 0.0f;
    if (lane == 31) wmax[warp] = ai;
    __syncthreads();
    if (warp == 0) {
        float w0 = wmax[lane], wi = w0;
#pragma unroll
        for (int d = 1; d < 32; d <<= 1) {
            float o = __shfl_up_sync(0xFFFFFFFFu, wi, d);
            if (lane >= d) wi = fmaxf(wi, o);
        }
        float e = __shfl_up_sync(0xFFFFFFFFu, wi, 1);
        if (lane == 0) e = 0.0f;
        wmax[lane] = e;
        if (lane == 31) s_gmax = wi;                      // global max precision
    }
    __syncthreads();
    float suf_excl = fmaxf(wmax[warp], le);
    s_suf[tid] = suf_excl;
    __syncthreads();
    float run = s_suf[1023 - tid];
    __syncthreads();

    // ---- weighted sum (descending within chunk, running suffix max) ----
    double s = 0.0;
    int hi = min(en, T);
    for (int p = hi - 1; p >= st; --p) {
        run = fmaxf(run, prec[p]);
        s += (double)run;
    }

    // ---- double reduction ----
#pragma unroll
    for (int d = 16; d; d >>= 1) s += __shfl_down_sync(0xFFFFFFFFu, s, d);
    if (lane == 0) wdbl[warp] = s;
    __syncthreads();
    if (warp == 0) {
        double t = wdbl[lane];
#pragma unroll
        for (int d = 16; d; d >>= 1) t += __shfl_down_sync(0xFFFFFFFFu, t, d);
        if (lane == 0) {
            if (s_c[0] == 1) t -= (double)s_gmax;         // rank-0 TP excluded
            out[z] = (float)(t / (double)(BB * GG));
            g_T[z] = 0;                                   // reset invariants for replay
            g_done2[z] = 0;
        }
    }
}

// ----------------------------------------------------------------------------
// Launcher (graph-capturable: kernels only, default stream)
// ----------------------------------------------------------------------------
extern "C" void kernel_launch(void* const* d_in, const int* in_sizes, int n_in,
                              void* d_out, int out_size) {
    const float*  scores = (const float*)d_in[0];
    const float2* segs   = (const float2*)d_in[1];
    const float2* gts    = (const float2*)d_in[2];
    float* out = (float*)d_out;

    const int smem_greedy = 2 * GG * NW * 4;               // 50,000 B dynamic
    // hist phase needs (2050 ints + TMAX keys); finalize overlays within this
    const int smem_hist   = 2050 * 4 + TMAX * 8;           // 110,600 B dynamic

    cudaFuncSetAttribute(k_greedy, cudaFuncAttributeMaxDynamicSharedMemorySize, smem_greedy);
    cudaFuncSetAttribute(k_hist,   cudaFuncAttributeMaxDynamicSharedMemorySize, smem_hist);

    // Pin both kernels to the same (max) L1/SMEM carveout so the two graph
    // nodes never trigger a per-SM carveout repartition between launches.
    cudaFuncSetAttribute(k_greedy, cudaFuncAttributePreferredSharedMemoryCarveout,
                         cudaSharedmemCarveoutMaxShared);
    cudaFuncSetAttribute(k_hist,   cudaFuncAttributePreferredSharedMemoryCarveout,
                         cudaSharedmemCarveoutMaxShared);

    k_greedy<<<BB, 512, smem_greedy>>>(segs, gts, scores);
    k_hist<<<dim3(148, 2), 1024, smem_hist>>>(scores, out);
}

// round 13
// speedup vs baseline: 1.8940x; 1.8940x over previous
#include <cuda_runtime.h>
#include <cuda_bf16.h>

// Problem constants (fixed by the reference setup).
#define BB   256
#define NN   4000
#define GG   50
#define M_TOT (BB * NN)      // 1,024,000 elements
#define TMAX  (BB * GG)      // 12,800 max TPs per threshold
#define NBKT  4096           // 12-bit value buckets (R11 operating point)
#define NW    125            // 32-bit words covering NN proposals (125*32 == 4000)

// ----------------------------------------------------------------------------
// Device scratch (static globals — zero-initialized at load; every counter is
// restored to zero by its consumer, so graph replays are deterministic)
// ----------------------------------------------------------------------------
__device__ unsigned long long g_list[2][TMAX];       // compacted TP keys (unordered)
__device__ unsigned long long g_sorted[2][TMAX];     // fully sorted ascending keys
__device__ int g_T[2];                               // TP counts
__device__ __align__(16) int g_bcount[2][NBKT];      // bucket counts (filled by greedy)
__device__ int g_boff[2][NBKT + 1];                  // bucket offsets
__device__ int g_c[2][TMAX + 1];                     // lower-bound histogram
__device__ int g_done2[2];                           // hist completion counters

// ----------------------------------------------------------------------------
// Key: ascending key == (conf descending, index ascending).
// Layout: [conf-ord 32][idx 20][bucket 12]; bucket is monotone with the key.
// ----------------------------------------------------------------------------
__device__ __forceinline__ unsigned int ford(float f) {
    unsigned int u = __float_as_uint(f);
    return (u & 0x80000000u) ? ~u : (u | 0x80000000u);   // ascending float order
}
__device__ __forceinline__ int bucket_of(float conf) {
    int bi = (int)(conf * 4096.0f);
    bi = bi < 0 ? 0 : (bi > 4095 ? 4095 : bi);
    return 4095 - bi;                                     // higher conf -> smaller bucket
}
__device__ __forceinline__ unsigned long long make_key(float conf, int idx) {
    unsigned int kh = ~ford(conf);                        // ascending kh == descending conf
    return ((unsigned long long)kh << 32)
         | ((unsigned long long)(unsigned int)idx << 12)
         | (unsigned long long)bucket_of(conf);
}

// ----------------------------------------------------------------------------
// K1: greedy matching per batch + TP-key emission (identical to R11).
// ----------------------------------------------------------------------------
__global__ void __launch_bounds__(512) k_greedy(const float2* __restrict__ segs,
                                                const float2* __restrict__ gts,
                                                const float*  __restrict__ scores) {
    const int b = blockIdx.x, tid = threadIdx.x;
    const int lane = tid & 31, warp = tid >> 5;           // 16 warps
    extern __shared__ unsigned int pot[];                 // [2][GG][NW]
    __shared__ float4 sgt[GG];                            // sorted: {x, y, len, idx-bits}
    __shared__ float2 raw[GG];
    __shared__ unsigned int suse[2][NW];
    __shared__ int s_tab[64];
    __shared__ int s_maxlen;                              // float bits (positive)
    __shared__ int s_cnt[2], s_base[2];

    // zero bitmaps + zero this launch's g_c slice (distributed over 256 blocks)
    for (int i = tid; i < 2 * GG * NW; i += 512) pot[i] = 0u;
    for (int i = b * 512 + tid; i < 2 * (TMAX + 1); i += BB * 512) ((int*)g_c)[i] = 0;
    if (tid == 0) s_maxlen = 0;
    if (tid < 2) s_cnt[tid] = 0;
    if (tid < GG) raw[tid] = gts[b * GG + tid];
    __syncthreads();

    // sort gts by start (rank sort, stable on ties) + max length
    if (tid < GG) {
        float2 t = raw[tid];
        int r = 0;
        for (int j = 0; j < GG; ++j) {
            float xj = raw[j].x;
            r += (xj < t.x) || (xj == t.x && j < tid);
        }
        sgt[r] = make_float4(t.x, t.y, t.y - t.x, __int_as_float(tid));
        atomicMax(&s_maxlen, __float_as_int(t.y - t.x)); // positive floats: int cmp ok
    }
    __syncthreads();
    // 64-entry start table: s_tab[q] = first j with sgt[j].x >= q/64
    if (tid < 64) {
        float thr = (float)tid * (1.0f / 64.0f);
        int j = 0;
        while (j < GG && sgt[j].x < thr) ++j;
        s_tab[tid] = j;
    }
    __syncthreads();
    const float maxlg = __int_as_float(s_maxlen);

    // ---- candidate evaluation over the pruned gt window ----
    for (int n = tid; n < NN; n += 512) {
        float2 s = segs[b * NN + n];
        float la = s.y - s.x;
        float xlo = s.x - maxlg;
        int q = (int)(xlo * 64.0f) - 1;                   // -1: conservative vs fp round-up
        q = q < 0 ? 0 : (q > 63 ? 63 : q);
        int w = n >> 5;
        unsigned int wbit = 1u << (n & 31);
        for (int j = s_tab[q]; j < GG; ++j) {
            float4 t = sgt[j];                            // LDS.128
            if (t.x >= s.y) break;                        // inter <= 0 beyond here
            float inter = fminf(s.y, t.y) - fmaxf(s.x, t.x);
            float ssum  = la + t.z;                       // la + lg (> 0)
            int g = __float_as_int(t.w);
            // iou > 0.5 <=> 3*inter > la+lg ; iou > 0.75 <=> 7*inter > 3*(la+lg)
            if (3.0f * inter > ssum)         atomicOr(&pot[g * NW + w], wbit);
            if (7.0f * inter > 3.0f * ssum)  atomicOr(&pot[(GG + g) * NW + w], wbit);
        }
    }
    __syncthreads();

    // ---- greedy claims: one warp per threshold, used bits in registers ----
    if (warp < 2) {
        const int z = warp;
        unsigned int usedreg[4] = {0u, 0u, 0u, 0u};
        const unsigned int* P = pot + z * GG * NW;
        for (int g = 0; g < GG; ++g) {
            unsigned int best = 0xFFFFFFFFu;
#pragma unroll
            for (int s = 0; s < 4; ++s) {
                int w = s * 32 + lane;
                if (w < NW) {
                    unsigned int c = P[g * NW + w] & ~usedreg[s];
                    if (c) best = min(best, (unsigned int)(w * 32 + __ffs(c) - 1));
                }
            }
            unsigned int m = __reduce_min_sync(0xFFFFFFFFu, best);
            if (m != 0xFFFFFFFFu) {
                int wm = (int)(m >> 5);
                if ((wm & 31) == lane) usedreg[wm >> 5] |= 1u << (m & 31);
            }
        }
#pragma unroll
        for (int s = 0; s < 4; ++s) {
            int w = s * 32 + lane;
            if (w < NW) suse[z][w] = usedreg[s];
        }
    }
    __syncthreads();

    // ---- emit TP keys: block-aggregated reservation (1 global atomic per z) --
    int z = -1, w = 0, cnt = 0, lbase = 0;
    unsigned int word = 0;
    if (tid < 2 * NW) {
        z = tid / NW; w = tid % NW;
        word = suse[z][w];
        cnt = __popc(word);
        if (cnt) lbase = atomicAdd(&s_cnt[z], cnt);       // smem offsets
    }
    __syncthreads();
    if (tid < 2) s_base[tid] = s_cnt[tid] ? atomicAdd(&g_T[tid], s_cnt[tid]) : 0;
    __syncthreads();
    if (cnt) {
        int p = s_base[z] + lbase;
        while (word) {
            int bit = __ffs(word) - 1;
            word &= word - 1;
            int idx = b * NN + w * 32 + bit;
            unsigned long long key = make_key(scores[idx], idx);
            g_list[z][p++] = key;
            atomicAdd(&g_bcount[z][(int)(key & 0xFFFull)], 1);
        }
    }
}

// ----------------------------------------------------------------------------
// K2 (fused sort): one block per threshold (identical to R11).
// SMEM layout (ints): off[0..NBKT] | pad to 16B | fill[NBKT] | skeys (8B-aligned)
// ----------------------------------------------------------------------------
__global__ void __launch_bounds__(1024) k_sort() {
    const int z = blockIdx.x, tid = threadIdx.x;
    const int lane = tid & 31, warp = tid >> 5;
    extern __shared__ int ssort[];
    int* off  = ssort;                                    // NBKT+1 ints
    int* fill = ssort + NBKT + 4;                         // byte 16400 = 16-aligned
    unsigned long long* skeys = (unsigned long long*)(ssort + 2 * NBKT + 4); // 8-aligned
    __shared__ int wtot[32];

    int T = g_T[z];

    // load 4 consecutive bucket counts (g_bcount 16-aligned), restore to zero
    int4* bc = (int4*)&g_bcount[z][0];
    int4 c4 = bc[tid];
    bc[tid] = make_int4(0, 0, 0, 0);
    ((int4*)fill)[tid] = make_int4(0, 0, 0, 0);

    // block-wide exclusive scan over 4096 bins (4 per thread)
    int loc[4]; int s = 0;
    loc[0] = s; s += c4.x; loc[1] = s; s += c4.y;
    loc[2] = s; s += c4.z; loc[3] = s; s += c4.w;
    int v = s;
#pragma unroll
    for (int d = 1; d < 32; d <<= 1) {
        int o = __shfl_up_sync(0xFFFFFFFFu, v, d);
        if (lane >= d) v += o;
    }
    if (lane == 31) wtot[warp] = v;
    __syncthreads();
    if (warp == 0) {
        int w = wtot[lane], wi = w;
#pragma unroll
        for (int d = 1; d < 32; d <<= 1) {
            int o = __shfl_up_sync(0xFFFFFFFFu, wi, d);
            if (lane >= d) wi += o;
        }
        wtot[lane] = wi - w;
    }
    __syncthreads();
    int excl = wtot[warp] + (v - s);
    int base = tid * 4;
#pragma unroll
    for (int j = 0; j < 4; ++j) off[base + j] = excl + loc[j];
    if (tid == 1023) off[NBKT] = excl + s;
    __syncthreads();

    // single global pass: keys -> registers -> smem scatter
    for (int i = tid; i < T; i += 1024) {
        unsigned long long k = g_list[z][i];
        int bk = (int)(k & 0xFFFull);
        skeys[off[bk] + atomicAdd(&fill[bk], 1)] = k;
    }
    __syncthreads();

    // thread-per-bucket rank sort (avg ~3 keys/bucket)
    for (int bk = tid; bk < NBKT; bk += 1024) {
        int st = off[bk], en = off[bk + 1];
        for (int i = st; i < en; ++i) {
            unsigned long long k = skeys[i];
            int r = 0;
            for (int j = st; j < en; ++j) r += (skeys[j] < k) ? 1 : 0;
            g_sorted[z][st + r] = k;
        }
    }

    for (int i = tid; i <= NBKT; i += 1024) g_boff[z][i] = off[i];
}

// ----------------------------------------------------------------------------
// K3: lower-bound histogram (R11 operating point: NBKT=4096, same smem, same
// grid) + fused finalize in the LAST block per threshold. This is the ONLY
// structural change vs R11.
// Dynamic layout (hist):  soff[0..4096] | sk[TMAX] (8B-aligned at int 4098)
// Dynamic layout (final): s_c[TMAX+1] | prec[TMAX] | s_suf[1024]  (106.5KB)
// ----------------------------------------------------------------------------
__global__ void __launch_bounds__(1024) k_hist(const float* __restrict__ scores,
                                               float* __restrict__ out) {
    const int z = blockIdx.y, tid = threadIdx.x;
    const int lane = tid & 31, warp = tid >> 5;
    extern __shared__ int sh[];
    int* soff = sh;                                       // NBKT+1
    unsigned long long* sk = (unsigned long long*)(sh + NBKT + 2); // byte 16392, 8-aligned
    __shared__ int s_last;
    __shared__ int    wsum[32];
    __shared__ float  wmax[32];
    __shared__ double wdbl[32];
    __shared__ float  s_gmax;

    int T = g_T[z];
    for (int i = tid; i < T; i += 1024) sk[i] = g_sorted[z][i];
    for (int i = tid; i <= NBKT; i += 1024) soff[i] = g_boff[z][i];
    __syncthreads();

    // ---- histogram: in-bucket lower bound == global lower bound ----
    int stride = gridDim.x * 1024;
    for (int idx = blockIdx.x * 1024 + tid; idx < M_TOT; idx += stride) {
        unsigned long long key = make_key(__ldg(&scores[idx]), idx);
        int bk = (int)(key & 0xFFFull);
        int lo = soff[bk], hi = soff[bk + 1];
        while (lo < hi) {
            int mid = (lo + hi) >> 1;
            if (sk[mid] < key) lo = mid + 1; else hi = mid;
        }
        if (lo < T) atomicAdd(&g_c[z][lo], 1);            // bin T is never consumed
    }

    // ---- last-block election (per z) ----
    __threadfence();
    __syncthreads();
    if (tid == 0) s_last = (atomicAdd(&g_done2[z], 1) == (int)gridDim.x - 1);
    __syncthreads();
    if (!s_last) return;

    // ======================= FINALIZE (last block per z) ====================
    int*   s_c   = sh;                                    // TMAX+1 (+pad)
    float* prec  = (float*)(sh + TMAX + 4);               // TMAX
    float* s_suf = (float*)(sh + 2 * TMAX + 4);           // 1024

    if (T == 0) { if (tid == 0) { out[z] = 0.0f; g_T[z] = 0; g_done2[z] = 0; } return; }
    int bins = T + 1;

    __syncthreads();                                      // done with soff/sk
    for (int i = tid; i < bins; i += 1024) s_c[i] = g_c[z][i];  // coalesced stage
    __syncthreads();

    int CH = (bins + 1023) >> 10;
    int st = min(tid * CH, bins), en = min(st + CH, bins);

    // ---- block-wide exclusive prefix sum of per-thread bin sums ----
    int ssum = 0;
    for (int p = st; p < en; ++p) ssum += s_c[p];
    int v = ssum;
#pragma unroll
    for (int d = 1; d < 32; d <<= 1) {
        int o = __shfl_up_sync(0xFFFFFFFFu, v, d);
        if (lane >= d) v += o;
    }
    if (lane == 31) wsum[warp] = v;
    __syncthreads();
    if (warp == 0) {
        int w = wsum[lane], wi = w;
#pragma unroll
        for (int d = 1; d < 32; d <<= 1) {
            int o = __shfl_up_sync(0xFFFFFFFFu, wi, d);
            if (lane >= d) wi += o;
        }
        wsum[lane] = wi - w;
    }
    __syncthreads();
    int C = wsum[warp] + (v - ssum);

    // ---- precision values + chunk max ----
    float mx = 0.0f;
    for (int p = st; p < en; ++p) {
        C += s_c[p];
        if (p < T) {
            float pr = (float)(p + 1) / (float)C;
            prec[p] = pr;
            mx = fmaxf(mx, pr);
        }
    }

    // ---- exclusive suffix-max over chunks (reversed exclusive max-scan) ----
    s_suf[1023 - tid] = mx;
    __syncthreads();
    float a = s_suf[tid], ai = a;
#pragma unroll
    for (int d = 1; d < 32; d <<= 1) {
        float o = __shfl_up_sync(0xFFFFFFFFu, ai, d);
        if (lane >= d) ai = fmaxf(ai, o);
    }
    float le = __shfl_up_sync(0xFFFFFFFFu, ai, 1);
    if (lane == 0) le = 0.0f;
    if (lane == 31) wmax[warp] = ai;
    __syncthreads();
    if (warp == 0) {
        float w0 = wmax[lane], wi = w0;
#pragma unroll
        for (int d = 1; d < 32; d <<= 1) {
            float o = __shfl_up_sync(0xFFFFFFFFu, wi, d);
            if (lane >= d) wi = fmaxf(wi, o);
        }
        float e = __shfl_up_sync(0xFFFFFFFFu, wi, 1);
        if (lane == 0) e = 0.0f;
        wmax[lane] = e;
        if (lane == 31) s_gmax = wi;                      // global max precision
    }
    __syncthreads();
    float suf_excl = fmaxf(wmax[warp], le);
    s_suf[tid] = suf_excl;
    __syncthreads();
    float run = s_suf[1023 - tid];
    __syncthreads();

    // ---- weighted sum (descending within chunk, running suffix max) ----
    double s = 0.0;
    int hi = min(en, T);
    for (int p = hi - 1; p >= st; --p) {
        run = fmaxf(run, prec[p]);
        s += (double)run;
    }

    // ---- double reduction ----
#pragma unroll
    for (int d = 16; d; d >>= 1) s += __shfl_down_sync(0xFFFFFFFFu, s, d);
    if (lane == 0) wdbl[warp] = s;
    __syncthreads();
    if (warp == 0) {
        double t = wdbl[lane];
#pragma unroll
        for (int d = 16; d; d >>= 1) t += __shfl_down_sync(0xFFFFFFFFu, t, d);
        if (lane == 0) {
            if (s_c[0] == 1) t -= (double)s_gmax;         // rank-0 TP excluded
            out[z] = (float)(t / (double)(BB * GG));
            g_T[z] = 0;                                   // reset invariants for replay
            g_done2[z] = 0;
        }
    }
}

// ----------------------------------------------------------------------------
// Launcher (graph-capturable: kernels only, default stream)
// ----------------------------------------------------------------------------
extern "C" void kernel_launch(void* const* d_in, const int* in_sizes, int n_in,
                              void* d_out, int out_size) {
    const float*  scores = (const float*)d_in[0];
    const float2* segs   = (const float2*)d_in[1];
    const float2* gts    = (const float2*)d_in[2];
    float* out = (float*)d_out;

    const int smem_greedy = 2 * GG * NW * 4;                       // 50,000 B
    const int smem_sort   = (2 * NBKT + 4) * 4 + TMAX * 8;         // 135,184 B
    const int smem_hist   = (NBKT + 2) * 4 + TMAX * 8;             // 118,792 B (R11 point)

    cudaFuncSetAttribute(k_greedy, cudaFuncAttributeMaxDynamicSharedMemorySize, smem_greedy);
    cudaFuncSetAttribute(k_sort,   cudaFuncAttributeMaxDynamicSharedMemorySize, smem_sort);
    cudaFuncSetAttribute(k_hist,   cudaFuncAttributeMaxDynamicSharedMemorySize, smem_hist);

    // Pin all kernels to the same (max) L1/SMEM carveout so consecutive graph
    // nodes never trigger a per-SM carveout repartition between launches.
    cudaFuncSetAttribute(k_greedy, cudaFuncAttributePreferredSharedMemoryCarveout,
                         cudaSharedmemCarveoutMaxShared);
    cudaFuncSetAttribute(k_sort,   cudaFuncAttributePreferredSharedMemoryCarveout,
                         cudaSharedmemCarveoutMaxShared);
    cudaFuncSetAttribute(k_hist,   cudaFuncAttributePreferredSharedMemoryCarveout,
                         cudaSharedmemCarveoutMaxShared);

    k_greedy<<<BB, 512, smem_greedy>>>(segs, gts, scores);
    k_sort<<<2, 1024, smem_sort>>>();
    k_hist<<<dim3(148, 2), 1024, smem_hist>>>(scores, out);
}

// round 14
// speedup vs baseline: 1.9512x; 1.0302x over previous
#include <cuda_runtime.h>
#include <cuda_bf16.h>

// Problem constants (fixed by the reference setup).
#define BB   256
#define NN   4000
#define GG   50
#define M_TOT (BB * NN)      // 1,024,000 elements
#define TMAX  (BB * GG)      // 12,800 max TPs per threshold
#define NBKT  2048           // 11-bit value buckets -> hist smem 110.6KB -> 2 blocks/SM
#define NW    125            // 32-bit words covering NN proposals (125*32 == 4000)

// ----------------------------------------------------------------------------
// Device scratch (static globals — zero-initialized at load; every counter is
// restored to zero by its consumer, so graph replays are deterministic)
// ----------------------------------------------------------------------------
__device__ unsigned long long g_list[2][TMAX];       // compacted TP keys (unordered)
__device__ unsigned long long g_sorted[2][TMAX];     // fully sorted ascending keys
__device__ int g_T[2];                               // TP counts
__device__ __align__(16) int g_bcount[2][NBKT];      // bucket counts (filled by greedy)
__device__ int g_boff[2][NBKT + 1];                  // bucket offsets
__device__ int g_c[2][TMAX + 1];                     // lower-bound histogram

// ----------------------------------------------------------------------------
// Key: ascending key == (conf descending, index ascending).
// Layout: [conf-ord 32][idx 20][bucket 12]; bucket (0..2047) monotone with key.
// ----------------------------------------------------------------------------
__device__ __forceinline__ unsigned int ford(float f) {
    unsigned int u = __float_as_uint(f);
    return (u & 0x80000000u) ? ~u : (u | 0x80000000u);   // ascending float order
}
__device__ __forceinline__ int bucket_of(float conf) {
    int bi = (int)(conf * 2048.0f);
    bi = bi < 0 ? 0 : (bi > 2047 ? 2047 : bi);
    return 2047 - bi;                                     // higher conf -> smaller bucket
}
__device__ __forceinline__ unsigned long long make_key(float conf, int idx) {
    unsigned int kh = ~ford(conf);                        // ascending kh == descending conf
    return ((unsigned long long)kh << 32)
         | ((unsigned long long)(unsigned int)idx << 12)
         | (unsigned long long)bucket_of(conf);
}

// ----------------------------------------------------------------------------
// K1: greedy matching per batch + TP-key emission. 1024 threads/block (vs 512
// in R11): same 50KB smem, 2 blocks/SM -> double the warps hiding the
// latency-bound gt-window loop. Claims/emission logic identical to R11.
// ----------------------------------------------------------------------------
__global__ void __launch_bounds__(1024) k_greedy(const float2* __restrict__ segs,
                                                 const float2* __restrict__ gts,
                                                 const float*  __restrict__ scores) {
    const int b = blockIdx.x, tid = threadIdx.x;
    const int lane = tid & 31, warp = tid >> 5;           // 32 warps
    extern __shared__ unsigned int pot[];                 // [2][GG][NW]
    __shared__ float4 sgt[GG];                            // sorted: {x, y, len, idx-bits}
    __shared__ float2 raw[GG];
    __shared__ unsigned int suse[2][NW];
    __shared__ int s_tab[64];
    __shared__ int s_maxlen;                              // float bits (positive)
    __shared__ int s_cnt[2], s_base[2];

    // zero bitmaps + zero this launch's g_c slice (distributed over 256 blocks)
    for (int i = tid; i < 2 * GG * NW; i += 1024) pot[i] = 0u;
    for (int i = b * 1024 + tid; i < 2 * (TMAX + 1); i += BB * 1024) ((int*)g_c)[i] = 0;
    if (tid == 0) s_maxlen = 0;
    if (tid < 2) s_cnt[tid] = 0;
    if (tid < GG) raw[tid] = gts[b * GG + tid];
    __syncthreads();

    // sort gts by start (rank sort, stable on ties) + max length
    if (tid < GG) {
        float2 t = raw[tid];
        int r = 0;
        for (int j = 0; j < GG; ++j) {
            float xj = raw[j].x;
            r += (xj < t.x) || (xj == t.x && j < tid);
        }
        sgt[r] = make_float4(t.x, t.y, t.y - t.x, __int_as_float(tid));
        atomicMax(&s_maxlen, __float_as_int(t.y - t.x)); // positive floats: int cmp ok
    }
    __syncthreads();
    // 64-entry start table: s_tab[q] = first j with sgt[j].x >= q/64
    if (tid < 64) {
        float thr = (float)tid * (1.0f / 64.0f);
        int j = 0;
        while (j < GG && sgt[j].x < thr) ++j;
        s_tab[tid] = j;
    }
    __syncthreads();
    const float maxlg = __int_as_float(s_maxlen);

    // ---- candidate evaluation over the pruned gt window ----
    for (int n = tid; n < NN; n += 1024) {
        float2 s = segs[b * NN + n];
        float la = s.y - s.x;
        float xlo = s.x - maxlg;
        int q = (int)(xlo * 64.0f) - 1;                   // -1: conservative vs fp round-up
        q = q < 0 ? 0 : (q > 63 ? 63 : q);
        int w = n >> 5;
        unsigned int wbit = 1u << (n & 31);
        for (int j = s_tab[q]; j < GG; ++j) {
            float4 t = sgt[j];                            // LDS.128
            if (t.x >= s.y) break;                        // inter <= 0 beyond here
            float inter = fminf(s.y, t.y) - fmaxf(s.x, t.x);
            float ssum  = la + t.z;                       // la + lg (> 0)
            int g = __float_as_int(t.w);
            // iou > 0.5 <=> 3*inter > la+lg ; iou > 0.75 <=> 7*inter > 3*(la+lg)
            if (3.0f * inter > ssum)         atomicOr(&pot[g * NW + w], wbit);
            if (7.0f * inter > 3.0f * ssum)  atomicOr(&pot[(GG + g) * NW + w], wbit);
        }
    }
    __syncthreads();

    // ---- greedy claims: one warp per threshold, used bits in registers ----
    if (warp < 2) {
        const int z = warp;
        unsigned int usedreg[4] = {0u, 0u, 0u, 0u};
        const unsigned int* P = pot + z * GG * NW;
        for (int g = 0; g < GG; ++g) {
            unsigned int best = 0xFFFFFFFFu;
#pragma unroll
            for (int s = 0; s < 4; ++s) {
                int w = s * 32 + lane;
                if (w < NW) {
                    unsigned int c = P[g * NW + w] & ~usedreg[s];
                    if (c) best = min(best, (unsigned int)(w * 32 + __ffs(c) - 1));
                }
            }
            unsigned int m = __reduce_min_sync(0xFFFFFFFFu, best);
            if (m != 0xFFFFFFFFu) {
                int wm = (int)(m >> 5);
                if ((wm & 31) == lane) usedreg[wm >> 5] |= 1u << (m & 31);
            }
        }
#pragma unroll
        for (int s = 0; s < 4; ++s) {
            int w = s * 32 + lane;
            if (w < NW) suse[z][w] = usedreg[s];
        }
    }
    __syncthreads();

    // ---- emit TP keys: block-aggregated reservation (1 global atomic per z) --
    int z = -1, w = 0, cnt = 0, lbase = 0;
    unsigned int word = 0;
    if (tid < 2 * NW) {
        z = tid / NW; w = tid % NW;
        word = suse[z][w];
        cnt = __popc(word);
        if (cnt) lbase = atomicAdd(&s_cnt[z], cnt);       // smem offsets
    }
    __syncthreads();
    if (tid < 2) s_base[tid] = s_cnt[tid] ? atomicAdd(&g_T[tid], s_cnt[tid]) : 0;
    __syncthreads();
    if (cnt) {
        int p = s_base[z] + lbase;
        while (word) {
            int bit = __ffs(word) - 1;
            word &= word - 1;
            int idx = b * NN + w * 32 + bit;
            unsigned long long key = make_key(scores[idx], idx);
            g_list[z][p++] = key;
            atomicAdd(&g_bcount[z][(int)(key & 0xFFFull)], 1);
        }
    }
}

// ----------------------------------------------------------------------------
// K2 (fused sort): one block per threshold (R11 logic, NBKT=2048: threads
// 0..511 each own 4 consecutive bins; the rest contribute zeros to the scan).
// SMEM layout (ints): off[0..NBKT] | pad to 16B | fill[NBKT] | skeys (8B-aligned)
// ----------------------------------------------------------------------------
__global__ void __launch_bounds__(1024) k_sort() {
    const int z = blockIdx.x, tid = threadIdx.x;
    const int lane = tid & 31, warp = tid >> 5;
    extern __shared__ int ssort[];
    int* off  = ssort;                                    // NBKT+1 ints
    int* fill = ssort + NBKT + 4;                         // byte 8208 = 16-aligned
    unsigned long long* skeys = (unsigned long long*)(ssort + 2 * NBKT + 4); // byte 16400, 8-aligned
    __shared__ int wtot[32];

    int T = g_T[z];

    // threads 0..511: load 4 consecutive bucket counts, restore them to zero
    int4 c4 = make_int4(0, 0, 0, 0);
    if (tid < NBKT / 4) {
        int4* bc = (int4*)&g_bcount[z][0];
        c4 = bc[tid];
        bc[tid] = make_int4(0, 0, 0, 0);
        ((int4*)fill)[tid] = make_int4(0, 0, 0, 0);
    }

    // block-wide exclusive scan (threads >= 512 contribute zeros)
    int loc[4]; int s = 0;
    loc[0] = s; s += c4.x; loc[1] = s; s += c4.y;
    loc[2] = s; s += c4.z; loc[3] = s; s += c4.w;
    int v = s;
#pragma unroll
    for (int d = 1; d < 32; d <<= 1) {
        int o = __shfl_up_sync(0xFFFFFFFFu, v, d);
        if (lane >= d) v += o;
    }
    if (lane == 31) wtot[warp] = v;
    __syncthreads();
    if (warp == 0) {
        int w = wtot[lane], wi = w;
#pragma unroll
        for (int d = 1; d < 32; d <<= 1) {
            int o = __shfl_up_sync(0xFFFFFFFFu, wi, d);
            if (lane >= d) wi += o;
        }
        wtot[lane] = wi - w;
    }
    __syncthreads();
    int excl = wtot[warp] + (v - s);
    if (tid < NBKT / 4) {
        int base = tid * 4;
#pragma unroll
        for (int j = 0; j < 4; ++j) off[base + j] = excl + loc[j];
    }
    if (tid == 1023) off[NBKT] = excl + s;                // s==0 here -> excl == total
    __syncthreads();

    // single global pass: keys -> registers -> smem scatter
    for (int i = tid; i < T; i += 1024) {
        unsigned long long k = g_list[z][i];
        int bk = (int)(k & 0xFFFull);
        skeys[off[bk] + atomicAdd(&fill[bk], 1)] = k;
    }
    __syncthreads();

    // thread-per-bucket rank sort (avg ~6 keys/bucket)
    for (int bk = tid; bk < NBKT; bk += 1024) {
        int st = off[bk], en = off[bk + 1];
        for (int i = st; i < en; ++i) {
            unsigned long long k = skeys[i];
            int r = 0;
            for (int j = st; j < en; ++j) r += (skeys[j] < k) ? 1 : 0;
            g_sorted[z][st + r] = k;
        }
    }

    for (int i = tid; i <= NBKT; i += 1024) g_boff[z][i] = off[i];
}

// ----------------------------------------------------------------------------
// K3: lower-bound histogram. NBKT=2048 buckets (~6 keys each, ~3 levels),
// smem 110.6KB -> 2 blocks/SM. FOUR independent searches interleaved per
// thread so the dependent-LDS chains overlap (MLP=4).
// ----------------------------------------------------------------------------
__global__ void __launch_bounds__(1024) k_hist(const float* __restrict__ scores) {
    const int z = blockIdx.y, tid = threadIdx.x;
    extern __shared__ int sh[];
    int* soff = sh;                                       // NBKT+1
    unsigned long long* sk = (unsigned long long*)(sh + NBKT + 2); // byte 8200, 8-aligned
    int T = g_T[z];
    for (int i = tid; i < T; i += 1024) sk[i] = g_sorted[z][i];
    for (int i = tid; i <= NBKT; i += 1024) soff[i] = g_boff[z][i];
    __syncthreads();

    const int stride = gridDim.x * 1024;
    for (int base = blockIdx.x * 1024 + tid; base < M_TOT; base += 4 * stride) {
        unsigned long long key[4]; int lo[4], hi[4];
#pragma unroll
        for (int k = 0; k < 4; ++k) {
            int i = base + k * stride;
            if (i < M_TOT) {
                unsigned long long kk = make_key(__ldg(&scores[i]), i);
                int bk = (int)(kk & 0xFFFull);
                key[k] = kk; lo[k] = soff[bk]; hi[k] = soff[bk + 1];
            } else { key[k] = 0; lo[k] = 0; hi[k] = 0; }
        }
        for (;;) {
            bool any = false;
#pragma unroll
            for (int k = 0; k < 4; ++k) {
                if (lo[k] < hi[k]) {
                    int mid = (lo[k] + hi[k]) >> 1;
                    if (sk[mid] < key[k]) lo[k] = mid + 1; else hi[k] = mid;
                }
            }
#pragma unroll
            for (int k = 0; k < 4; ++k) any = any || (lo[k] < hi[k]);
            if (!any) break;
        }
#pragma unroll
        for (int k = 0; k < 4; ++k) {
            int i = base + k * stride;
            if (i < M_TOT && lo[k] < T) atomicAdd(&g_c[z][lo[k]], 1);  // bin T unused
        }
    }
}

// ----------------------------------------------------------------------------
// K4: finalize AP per threshold (identical to R11). g_c staged into SMEM
// coalesced; chunked loops run out of SMEM. Resets g_T for the next replay.
// ----------------------------------------------------------------------------
__global__ void __launch_bounds__(1024) k_final(float* __restrict__ out) {
    const int z = blockIdx.x, tid = threadIdx.x;
    const int lane = tid & 31, warp = tid >> 5;
    __shared__ int    wsum[32];
    __shared__ float  wmax[32];
    __shared__ double wdbl[32];
    __shared__ float  s_suf[1024];
    __shared__ float  s_gmax;
    extern __shared__ int sfin[];
    int*   s_c  = sfin;                                   // TMAX+1 (+pad)
    float* prec = (float*)(sfin + TMAX + 4);              // TMAX

    int T = g_T[z];
    if (T == 0) { if (tid == 0) { out[z] = 0.0f; g_T[z] = 0; } return; }
    int bins = T + 1;

    // coalesced stage of the histogram
    for (int i = tid; i < bins; i += 1024) s_c[i] = g_c[z][i];
    __syncthreads();

    int CH = (bins + 1023) >> 10;
    int st = min(tid * CH, bins), en = min(st + CH, bins);

    // ---- block-wide exclusive prefix sum of per-thread bin sums ----
    int ssum = 0;
    for (int p = st; p < en; ++p) ssum += s_c[p];
    int v = ssum;
#pragma unroll
    for (int d = 1; d < 32; d <<= 1) {
        int o = __shfl_up_sync(0xFFFFFFFFu, v, d);
        if (lane >= d) v += o;
    }
    if (lane == 31) wsum[warp] = v;
    __syncthreads();
    if (warp == 0) {
        int w = wsum[lane], wi = w;
#pragma unroll
        for (int d = 1; d < 32; d <<= 1) {
            int o = __shfl_up_sync(0xFFFFFFFFu, wi, d);
            if (lane >= d) wi += o;
        }
        wsum[lane] = wi - w;
    }
    __syncthreads();
    int C = wsum[warp] + (v - ssum);

    // ---- precision values + chunk max ----
    float mx = 0.0f;
    for (int p = st; p < en; ++p) {
        C += s_c[p];
        if (p < T) {
            float pr = (float)(p + 1) / (float)C;
            prec[p] = pr;
            mx = fmaxf(mx, pr);
        }
    }

    // ---- exclusive suffix-max over chunks (reversed exclusive max-scan) ----
    s_suf[1023 - tid] = mx;
    __syncthreads();
    float a = s_suf[tid], ai = a;
#pragma unroll
    for (int d = 1; d < 32; d <<= 1) {
        float o = __shfl_up_sync(0xFFFFFFFFu, ai, d);
        if (lane >= d) ai = fmaxf(ai, o);
    }
    float le = __shfl_up_sync(0xFFFFFFFFu, ai, 1);
    if (lane == 0) le = 0.0f;
    if (lane == 31) wmax[warp] = ai;
    __syncthreads();
    if (warp == 0) {
        float w0 = wmax[lane], wi = w0;
#pragma unroll
        for (int d = 1; d < 32; d <<= 1) {
            float o = __shfl_up_sync(0xFFFFFFFFu, wi, d);
            if (lane >= d) wi = fmaxf(wi, o);
        }
        float e = __shfl_up_sync(0xFFFFFFFFu, wi, 1);
        if (lane == 0) e = 0.0f;
        wmax[lane] = e;
        if (lane == 31) s_gmax = wi;                      // global max precision
    }
    __syncthreads();
    float suf_excl = fmaxf(wmax[warp], le);
    s_suf[tid] = suf_excl;
    __syncthreads();
    float run = s_suf[1023 - tid];
    __syncthreads();

    // ---- weighted sum (descending within chunk, running suffix max) ----
    double s = 0.0;
    int hi = min(en, T);
    for (int p = hi - 1; p >= st; --p) {
        run = fmaxf(run, prec[p]);
        s += (double)run;
    }

    // ---- double reduction ----
#pragma unroll
    for (int d = 16; d; d >>= 1) s += __shfl_down_sync(0xFFFFFFFFu, s, d);
    if (lane == 0) wdbl[warp] = s;
    __syncthreads();
    if (warp == 0) {
        double t = wdbl[lane];
#pragma unroll
        for (int d = 16; d; d >>= 1) t += __shfl_down_sync(0xFFFFFFFFu, t, d);
        if (lane == 0) {
            if (s_c[0] == 1) t -= (double)s_gmax;         // rank-0 TP excluded
            out[z] = (float)(t / (double)(BB * GG));
            g_T[z] = 0;                                   // restore invariant for replay
        }
    }
}

// ----------------------------------------------------------------------------
// Launcher (graph-capturable: kernels only, default stream)
// ----------------------------------------------------------------------------
extern "C" void kernel_launch(void* const* d_in, const int* in_sizes, int n_in,
                              void* d_out, int out_size) {
    const float*  scores = (const float*)d_in[0];
    const float2* segs   = (const float2*)d_in[1];
    const float2* gts    = (const float2*)d_in[2];
    float* out = (float*)d_out;

    const int smem_greedy = 2 * GG * NW * 4;                       // 50,000 B
    const int smem_sort   = (2 * NBKT + 4) * 4 + TMAX * 8;         // 118,800 B
    const int smem_hist   = (NBKT + 2) * 4 + TMAX * 8;             // 110,600 B -> 2 blocks/SM
    const int smem_final  = (TMAX + 4 + TMAX) * 4;                 // 102,416 B

    cudaFuncSetAttribute(k_greedy, cudaFuncAttributeMaxDynamicSharedMemorySize, smem_greedy);
    cudaFuncSetAttribute(k_sort,   cudaFuncAttributeMaxDynamicSharedMemorySize, smem_sort);
    cudaFuncSetAttribute(k_hist,   cudaFuncAttributeMaxDynamicSharedMemorySize, smem_hist);
    cudaFuncSetAttribute(k_final,  cudaFuncAttributeMaxDynamicSharedMemorySize, smem_final);

    // Pin all kernels to the same (max) L1/SMEM carveout so consecutive graph
    // nodes never trigger a per-SM carveout repartition between launches.
    cudaFuncSetAttribute(k_greedy, cudaFuncAttributePreferredSharedMemoryCarveout,
                         cudaSharedmemCarveoutMaxShared);
    cudaFuncSetAttribute(k_sort,   cudaFuncAttributePreferredSharedMemoryCarveout,
                         cudaSharedmemCarveoutMaxShared);
    cudaFuncSetAttribute(k_hist,   cudaFuncAttributePreferredSharedMemoryCarveout,
                         cudaSharedmemCarveoutMaxShared);
    cudaFuncSetAttribute(k_final,  cudaFuncAttributePreferredSharedMemoryCarveout,
                         cudaSharedmemCarveoutMaxShared);

    k_greedy<<<BB, 1024, smem_greedy>>>(segs, gts, scores);
    k_sort<<<2, 1024, smem_sort>>>();
    k_hist<<<dim3(148, 2), 1024, smem_hist>>>(scores);
    k_final<<<2, 1024, smem_final>>>(out);
}

// round 15
// speedup vs baseline: 2.1843x; 1.1195x over previous
#include <cuda_runtime.h>
#include <cuda_bf16.h>

// Problem constants (fixed by the reference setup).
#define BB   256
#define NN   4000
#define GG   50
#define M_TOT (BB * NN)      // 1,024,000 elements
#define TMAX  (BB * GG)      // 12,800 max TPs per threshold
#define NBKT  4096           // 12-bit value buckets (R11 operating point)
#define NW    125            // 32-bit words covering NN proposals (125*32 == 4000)

// ----------------------------------------------------------------------------
// Device scratch (static globals — zero-initialized at load; every counter is
// restored to zero by its consumer, so graph replays are deterministic)
// ----------------------------------------------------------------------------
__device__ unsigned long long g_list[2][TMAX];       // compacted TP keys (unordered)
__device__ unsigned long long g_sorted[2][TMAX];     // fully sorted ascending keys
__device__ int g_T[2];                               // TP counts
__device__ __align__(16) int g_bcount[2][NBKT];      // bucket counts (filled by greedy)
__device__ int g_boff[2][NBKT + 1];                  // bucket offsets
__device__ int g_c[2][TMAX + 1];                     // lower-bound histogram

// ----------------------------------------------------------------------------
// Key: ascending key == (conf descending, index ascending).
// Layout: [conf-ord 32][idx 20][bucket 12]; bucket is monotone with the key.
// ----------------------------------------------------------------------------
__device__ __forceinline__ unsigned int ford(float f) {
    unsigned int u = __float_as_uint(f);
    return (u & 0x80000000u) ? ~u : (u | 0x80000000u);   // ascending float order
}
__device__ __forceinline__ int bucket_of(float conf) {
    int bi = (int)(conf * 4096.0f);
    bi = bi < 0 ? 0 : (bi > 4095 ? 4095 : bi);
    return 4095 - bi;                                     // higher conf -> smaller bucket
}
__device__ __forceinline__ unsigned long long make_key(float conf, int idx) {
    unsigned int kh = ~ford(conf);                        // ascending kh == descending conf
    return ((unsigned long long)kh << 32)
         | ((unsigned long long)(unsigned int)idx << 12)
         | (unsigned long long)bucket_of(conf);
}

// ----------------------------------------------------------------------------
// K1: greedy matching per batch + TP-key emission.
//   NEW vs R11: proposals are bucket-sorted by start (64-bin counting sort in
//   SMEM) so each warp's 32 lanes hold spatially-adjacent proposals; the
//   gt-window loop is then UNIFORM across the warp (~13 of 50 gts) instead of
//   a divergent union (~50). Passing lanes scatter sparse atomicOr into the
//   ORIGINAL-index bitmap, so claims/emission and all downstream semantics
//   are bit-identical to R11.
// Dynamic SMEM: pot[2*GG*NW] ints (50,000B) | sxy[NN] float2 (32,000B)
//               | sn[NN] ushort (8,000B)  => 90,000B
// ----------------------------------------------------------------------------
__global__ void __launch_bounds__(512) k_greedy(const float2* __restrict__ segs,
                                                const float2* __restrict__ gts,
                                                const float*  __restrict__ scores) {
    const int b = blockIdx.x, tid = threadIdx.x;
    const int lane = tid & 31, warp = tid >> 5;           // 16 warps
    extern __shared__ unsigned int pot[];                 // [2][GG][NW]
    float2*         sxy = (float2*)(pot + 2 * GG * NW);   // byte 50,000 (8-aligned)
    unsigned short* sn  = (unsigned short*)(sxy + NN);    // byte 82,000
    __shared__ float4 sgt[GG];                            // sorted: {x, y, len, idx-bits}
    __shared__ float2 raw[GG];
    __shared__ unsigned int suse[2][NW];
    __shared__ int s_tab[64];
    __shared__ int s_maxlen;                              // float bits (positive)
    __shared__ int s_cnt[2], s_base[2];
    __shared__ int s_cnt64[64], s_off64[64], s_fill64[64];

    // zero bitmaps + zero this launch's g_c slice (distributed over 256 blocks)
    for (int i = tid; i < 2 * GG * NW; i += 512) pot[i] = 0u;
    for (int i = b * 512 + tid; i < 2 * (TMAX + 1); i += BB * 512) ((int*)g_c)[i] = 0;
    if (tid == 0) s_maxlen = 0;
    if (tid < 2) s_cnt[tid] = 0;
    if (tid < 64) { s_cnt64[tid] = 0; s_fill64[tid] = 0; }
    if (tid < GG) raw[tid] = gts[b * GG + tid];
    __syncthreads();

    // sort gts by start (rank sort, stable on ties) + max length
    if (tid < GG) {
        float2 t = raw[tid];
        int r = 0;
        for (int j = 0; j < GG; ++j) {
            float xj = raw[j].x;
            r += (xj < t.x) || (xj == t.x && j < tid);
        }
        sgt[r] = make_float4(t.x, t.y, t.y - t.x, __int_as_float(tid));
        atomicMax(&s_maxlen, __float_as_int(t.y - t.x)); // positive floats: int cmp ok
    }

    // counting-sort pass A: bin counts of proposal starts (64 bins over [0,1))
    for (int n = tid; n < NN; n += 512) {
        float sx = segs[b * NN + n].x;
        int bq = (int)(sx * 64.0f);
        bq = bq < 0 ? 0 : (bq > 63 ? 63 : bq);
        atomicAdd(&s_cnt64[bq], 1);
    }
    __syncthreads();

    // 64-entry gt start table + 64-bin exclusive scan (warp 0)
    if (tid < 64) {
        float thr = (float)tid * (1.0f / 64.0f);
        int j = 0;
        while (j < GG && sgt[j].x < thr) ++j;
        s_tab[tid] = j;
    }
    if (warp == 0) {
        int c0 = s_cnt64[lane * 2], c1 = s_cnt64[lane * 2 + 1];
        int s2 = c0 + c1, v = s2;
#pragma unroll
        for (int d = 1; d < 32; d <<= 1) {
            int o = __shfl_up_sync(0xFFFFFFFFu, v, d);
            if (lane >= d) v += o;
        }
        int excl = v - s2;
        s_off64[lane * 2] = excl;
        s_off64[lane * 2 + 1] = excl + c0;
    }
    __syncthreads();
    const float maxlg = __int_as_float(s_maxlen);

    // counting-sort pass B: scatter proposals into start-sorted order
    for (int n = tid; n < NN; n += 512) {
        float2 s = segs[b * NN + n];
        int bq = (int)(s.x * 64.0f);
        bq = bq < 0 ? 0 : (bq > 63 ? 63 : bq);
        int pos = s_off64[bq] + atomicAdd(&s_fill64[bq], 1);
        sxy[pos] = s;
        sn[pos] = (unsigned short)n;
    }
    __syncthreads();

    // ---- candidate evaluation: warp-uniform gt window over sorted chunks ----
    for (int ch = warp; ch < NW; ch += 16) {              // 125 chunks of 32
        int i = ch * 32 + lane;                           // always < 4000
        float2 s = sxy[i];
        int n = sn[i];
        float la = s.y - s.x;
        int wn = n >> 5;
        unsigned int bitn = 1u << (n & 31);

        float xlo = s.x - maxlg;
        int q = (int)(xlo * 64.0f) - 1;                   // -1: conservative vs fp round-up
        q = q < 0 ? 0 : (q > 63 ? 63 : q);
        int j0 = s_tab[q];
        int jmin = __reduce_min_sync(0xFFFFFFFFu, j0);
        int symax_i = __reduce_max_sync(0xFFFFFFFFu, __float_as_int(s.y)); // s.y > 0
        float symax = __int_as_float(symax_i);

        for (int j = jmin; j < GG; ++j) {
            float4 t = sgt[j];                            // uniform broadcast LDS.128
            if (t.x >= symax) break;                      // uniform exit: inter<=0 for all
            float inter = fminf(s.y, t.y) - fmaxf(s.x, t.x);
            float ssum  = la + t.z;                       // la + lg (> 0)
            int g = __float_as_int(t.w);
            // iou > 0.5 <=> 3*inter > la+lg ; iou > 0.75 <=> 7*inter > 3*(la+lg)
            if (3.0f * inter > ssum)         atomicOr(&pot[g * NW + wn], bitn);
            if (7.0f * inter > 3.0f * ssum)  atomicOr(&pot[(GG + g) * NW + wn], bitn);
        }
    }
    __syncthreads();

    // ---- greedy claims: one warp per threshold, used bits in registers ----
    if (warp < 2) {
        const int z = warp;
        unsigned int usedreg[4] = {0u, 0u, 0u, 0u};
        const unsigned int* P = pot + z * GG * NW;
        for (int g = 0; g < GG; ++g) {
            unsigned int best = 0xFFFFFFFFu;
#pragma unroll
            for (int s = 0; s < 4; ++s) {
                int w = s * 32 + lane;
                if (w < NW) {
                    unsigned int c = P[g * NW + w] & ~usedreg[s];
                    if (c) best = min(best, (unsigned int)(w * 32 + __ffs(c) - 1));
                }
            }
            unsigned int m = __reduce_min_sync(0xFFFFFFFFu, best);
            if (m != 0xFFFFFFFFu) {
                int wm = (int)(m >> 5);
                if ((wm & 31) == lane) usedreg[wm >> 5] |= 1u << (m & 31);
            }
        }
#pragma unroll
        for (int s = 0; s < 4; ++s) {
            int w = s * 32 + lane;
            if (w < NW) suse[z][w] = usedreg[s];
        }
    }
    __syncthreads();

    // ---- emit TP keys: block-aggregated reservation (1 global atomic per z) --
    int z = -1, w = 0, cnt = 0, lbase = 0;
    unsigned int word = 0;
    if (tid < 2 * NW) {
        z = tid / NW; w = tid % NW;
        word = suse[z][w];
        cnt = __popc(word);
        if (cnt) lbase = atomicAdd(&s_cnt[z], cnt);       // smem offsets
    }
    __syncthreads();
    if (tid < 2) s_base[tid] = s_cnt[tid] ? atomicAdd(&g_T[tid], s_cnt[tid]) : 0;
    __syncthreads();
    if (cnt) {
        int p = s_base[z] + lbase;
        while (word) {
            int bit = __ffs(word) - 1;
            word &= word - 1;
            int idx = b * NN + w * 32 + bit;
            unsigned long long key = make_key(scores[idx], idx);
            g_list[z][p++] = key;
            atomicAdd(&g_bcount[z][(int)(key & 0xFFFull)], 1);
        }
    }
}

// ----------------------------------------------------------------------------
// K2 (fused sort): one block per threshold (identical to R11).
// SMEM layout (ints): off[0..NBKT] | pad to 16B | fill[NBKT] | skeys (8B-aligned)
// ----------------------------------------------------------------------------
__global__ void __launch_bounds__(1024) k_sort() {
    const int z = blockIdx.x, tid = threadIdx.x;
    const int lane = tid & 31, warp = tid >> 5;
    extern __shared__ int ssort[];
    int* off  = ssort;                                    // NBKT+1 ints
    int* fill = ssort + NBKT + 4;                         // byte 16400 = 16-aligned
    unsigned long long* skeys = (unsigned long long*)(ssort + 2 * NBKT + 4); // 8-aligned
    __shared__ int wtot[32];

    int T = g_T[z];

    // load 4 consecutive bucket counts (g_bcount 16-aligned), restore to zero
    int4* bc = (int4*)&g_bcount[z][0];
    int4 c4 = bc[tid];
    bc[tid] = make_int4(0, 0, 0, 0);
    ((int4*)fill)[tid] = make_int4(0, 0, 0, 0);

    // block-wide exclusive scan over 4096 bins (4 per thread)
    int loc[4]; int s = 0;
    loc[0] = s; s += c4.x; loc[1] = s; s += c4.y;
    loc[2] = s; s += c4.z; loc[3] = s; s += c4.w;
    int v = s;
#pragma unroll
    for (int d = 1; d < 32; d <<= 1) {
        int o = __shfl_up_sync(0xFFFFFFFFu, v, d);
        if (lane >= d) v += o;
    }
    if (lane == 31) wtot[warp] = v;
    __syncthreads();
    if (warp == 0) {
        int w = wtot[lane], wi = w;
#pragma unroll
        for (int d = 1; d < 32; d <<= 1) {
            int o = __shfl_up_sync(0xFFFFFFFFu, wi, d);
            if (lane >= d) wi += o;
        }
        wtot[lane] = wi - w;
    }
    __syncthreads();
    int excl = wtot[warp] + (v - s);
    int base = tid * 4;
#pragma unroll
    for (int j = 0; j < 4; ++j) off[base + j] = excl + loc[j];
    if (tid == 1023) off[NBKT] = excl + s;
    __syncthreads();

    // single global pass: keys -> registers -> smem scatter
    for (int i = tid; i < T; i += 1024) {
        unsigned long long k = g_list[z][i];
        int bk = (int)(k & 0xFFFull);
        skeys[off[bk] + atomicAdd(&fill[bk], 1)] = k;
    }
    __syncthreads();

    // thread-per-bucket rank sort (avg ~3 keys/bucket)
    for (int bk = tid; bk < NBKT; bk += 1024) {
        int st = off[bk], en = off[bk + 1];
        for (int i = st; i < en; ++i) {
            unsigned long long k = skeys[i];
            int r = 0;
            for (int j = st; j < en; ++j) r += (skeys[j] < k) ? 1 : 0;
            g_sorted[z][st + r] = k;
        }
    }

    for (int i = tid; i <= NBKT; i += 1024) g_boff[z][i] = off[i];
}

// ----------------------------------------------------------------------------
// K3: lower-bound histogram (identical to R11). 4096-way bucket narrows the
// search to ~3 keys. In-bucket lower bound == global lower bound.
// ----------------------------------------------------------------------------
__global__ void __launch_bounds__(1024) k_hist(const float* __restrict__ scores) {
    const int z = blockIdx.y;
    extern __shared__ int sh[];
    int* soff = sh;                                       // NBKT+1
    unsigned long long* sk = (unsigned long long*)(sh + NBKT + 2); // 8-aligned
    int T = g_T[z];
    for (int i = threadIdx.x; i < T; i += 1024) sk[i] = g_sorted[z][i];
    for (int i = threadIdx.x; i <= NBKT; i += 1024) soff[i] = g_boff[z][i];
    __syncthreads();

    int stride = gridDim.x * 1024;
    for (int idx = blockIdx.x * 1024 + threadIdx.x; idx < M_TOT; idx += stride) {
        unsigned long long key = make_key(__ldg(&scores[idx]), idx);
        int bk = (int)(key & 0xFFFull);
        int lo = soff[bk], hi = soff[bk + 1];
        while (lo < hi) {
            int mid = (lo + hi) >> 1;
            if (sk[mid] < key) lo = mid + 1; else hi = mid;
        }
        atomicAdd(&g_c[z][lo], 1);
    }
}

// ----------------------------------------------------------------------------
// K4: finalize AP per threshold (identical to R11). g_c staged into SMEM
// coalesced; chunked loops run out of SMEM. Resets g_T for the next replay.
// ----------------------------------------------------------------------------
__global__ void __launch_bounds__(1024) k_final(float* __restrict__ out) {
    const int z = blockIdx.x, tid = threadIdx.x;
    const int lane = tid & 31, warp = tid >> 5;
    __shared__ int    wsum[32];
    __shared__ float  wmax[32];
    __shared__ double wdbl[32];
    __shared__ float  s_suf[1024];
    __shared__ float  s_gmax;
    extern __shared__ int sfin[];
    int*   s_c  = sfin;                                   // TMAX+1 (+pad)
    float* prec = (float*)(sfin + TMAX + 4);              // TMAX

    int T = g_T[z];
    if (T == 0) { if (tid == 0) { out[z] = 0.0f; g_T[z] = 0; } return; }
    int bins = T + 1;

    // coalesced stage of the histogram
    for (int i = tid; i < bins; i += 1024) s_c[i] = g_c[z][i];
    __syncthreads();

    int CH = (bins + 1023) >> 10;
    int st = min(tid * CH, bins), en = min(st + CH, bins);

    // ---- block-wide exclusive prefix sum of per-thread bin sums ----
    int ssum = 0;
    for (int p = st; p < en; ++p) ssum += s_c[p];
    int v = ssum;
#pragma unroll
    for (int d = 1; d < 32; d <<= 1) {
        int o = __shfl_up_sync(0xFFFFFFFFu, v, d);
        if (lane >= d) v += o;
    }
    if (lane == 31) wsum[warp] = v;
    __syncthreads();
    if (warp == 0) {
        int w = wsum[lane], wi = w;
#pragma unroll
        for (int d = 1; d < 32; d <<= 1) {
            int o = __shfl_up_sync(0xFFFFFFFFu, wi, d);
            if (lane >= d) wi += o;
        }
        wsum[lane] = wi - w;
    }
    __syncthreads();
    int C = wsum[warp] + (v - ssum);

    // ---- precision values + chunk max ----
    float mx = 0.0f;
    for (int p = st; p < en; ++p) {
        C += s_c[p];
        if (p < T) {
            float pr = (float)(p + 1) / (float)C;
            prec[p] = pr;
            mx = fmaxf(mx, pr);
        }
    }

    // ---- exclusive suffix-max over chunks (reversed exclusive max-scan) ----
    s_suf[1023 - tid] = mx;
    __syncthreads();
    float a = s_suf[tid], ai = a;
#pragma unroll
    for (int d = 1; d < 32; d <<= 1) {
        float o = __shfl_up_sync(0xFFFFFFFFu, ai, d);
        if (lane >= d) ai = fmaxf(ai, o);
    }
    float le = __shfl_up_sync(0xFFFFFFFFu, ai, 1);
    if (lane == 0) le = 0.0f;
    if (lane == 31) wmax[warp] = ai;
    __syncthreads();
    if (warp == 0) {
        float w0 = wmax[lane], wi = w0;
#pragma unroll
        for (int d = 1; d < 32; d <<= 1) {
            float o = __shfl_up_sync(0xFFFFFFFFu, wi, d);
            if (lane >= d) wi = fmaxf(wi, o);
        }
        float e = __shfl_up_sync(0xFFFFFFFFu, wi, 1);
        if (lane == 0) e = 0.0f;
        wmax[lane] = e;
        if (lane == 31) s_gmax = wi;                      // global max precision
    }
    __syncthreads();
    float suf_excl = fmaxf(wmax[warp], le);
    s_suf[tid] = suf_excl;
    __syncthreads();
    float run = s_suf[1023 - tid];
    __syncthreads();

    // ---- weighted sum (descending within chunk, running suffix max) ----
    double s = 0.0;
    int hi = min(en, T);
    for (int p = hi - 1; p >= st; --p) {
        run = fmaxf(run, prec[p]);
        s += (double)run;
    }

    // ---- double reduction ----
#pragma unroll
    for (int d = 16; d; d >>= 1) s += __shfl_down_sync(0xFFFFFFFFu, s, d);
    if (lane == 0) wdbl[warp] = s;
    __syncthreads();
    if (warp == 0) {
        double t = wdbl[lane];
#pragma unroll
        for (int d = 16; d; d >>= 1) t += __shfl_down_sync(0xFFFFFFFFu, t, d);
        if (lane == 0) {
            if (s_c[0] == 1) t -= (double)s_gmax;         // rank-0 TP excluded
            out[z] = (float)(t / (double)(BB * GG));
            g_T[z] = 0;                                   // restore invariant for replay
        }
    }
}

// ----------------------------------------------------------------------------
// Launcher (graph-capturable: kernels only, default stream)
// ----------------------------------------------------------------------------
extern "C" void kernel_launch(void* const* d_in, const int* in_sizes, int n_in,
                              void* d_out, int out_size) {
    const float*  scores = (const float*)d_in[0];
    const float2* segs   = (const float2*)d_in[1];
    const float2* gts    = (const float2*)d_in[2];
    float* out = (float*)d_out;

    const int smem_greedy = 2 * GG * NW * 4 + NN * 8 + NN * 2;     //  90,000 B
    const int smem_sort   = (2 * NBKT + 4) * 4 + TMAX * 8;         // 135,184 B
    const int smem_hist   = (NBKT + 2) * 4 + TMAX * 8;             // 118,792 B (R11 point)
    const int smem_final  = (TMAX + 4 + TMAX) * 4;                 // 102,416 B

    cudaFuncSetAttribute(k_greedy, cudaFuncAttributeMaxDynamicSharedMemorySize, smem_greedy);
    cudaFuncSetAttribute(k_sort,   cudaFuncAttributeMaxDynamicSharedMemorySize, smem_sort);
    cudaFuncSetAttribute(k_hist,   cudaFuncAttributeMaxDynamicSharedMemorySize, smem_hist);
    cudaFuncSetAttribute(k_final,  cudaFuncAttributeMaxDynamicSharedMemorySize, smem_final);

    // Pin all kernels to the same (max) L1/SMEM carveout so consecutive graph
    // nodes never trigger a per-SM carveout repartition between launches.
    cudaFuncSetAttribute(k_greedy, cudaFuncAttributePreferredSharedMemoryCarveout,
                         cudaSharedmemCarveoutMaxShared);
    cudaFuncSetAttribute(k_sort,   cudaFuncAttributePreferredSharedMemoryCarveout,
                         cudaSharedmemCarveoutMaxShared);
    cudaFuncSetAttribute(k_hist,   cudaFuncAttributePreferredSharedMemoryCarveout,
                         cudaSharedmemCarveoutMaxShared);
    cudaFuncSetAttribute(k_final,  cudaFuncAttributePreferredSharedMemoryCarveout,
                         cudaSharedmemCarveoutMaxShared);

    k_greedy<<<BB, 512, smem_greedy>>>(segs, gts, scores);
    k_sort<<<2, 1024, smem_sort>>>();
    k_hist<<<dim3(148, 2), 1024, smem_hist>>>(scores);
    k_final<<<2, 1024, smem_final>>>(out);
}

// round 16
// speedup vs baseline: 2.1897x; 1.0025x over previous
#include <cuda_runtime.h>
#include <cuda_bf16.h>

// Problem constants (fixed by the reference setup).
#define BB   256
#define NN   4000
#define GG   50
#define M_TOT (BB * NN)      // 1,024,000 elements
#define TMAX  (BB * GG)      // 12,800 max TPs per threshold
#define NBKT  4096           // 12-bit value buckets (R11/R15 operating point)
#define NW    125            // 32-bit words covering NN proposals (125*32 == 4000)

// ----------------------------------------------------------------------------
// Device scratch (static globals — zero-initialized at load; every counter is
// restored to zero by its consumer, so graph replays are deterministic)
// ----------------------------------------------------------------------------
__device__ unsigned long long g_list[2][TMAX];       // compacted TP keys (unordered)
__device__ unsigned long long g_sorted[2][TMAX];     // fully sorted ascending keys
__device__ int g_T[2];                               // TP counts
__device__ __align__(16) int g_bcount[2][NBKT];      // bucket counts (filled by greedy)
__device__ int g_boff[2][NBKT + 1];                  // bucket offsets
__device__ int g_c[2][TMAX + 1];                     // lower-bound histogram

// ----------------------------------------------------------------------------
// Key: ascending key == (conf descending, index ascending).
// Layout: [conf-ord 32][idx 20][bucket 12]; bucket is monotone with the key.
// ----------------------------------------------------------------------------
__device__ __forceinline__ unsigned int ford(float f) {
    unsigned int u = __float_as_uint(f);
    return (u & 0x80000000u) ? ~u : (u | 0x80000000u);   // ascending float order
}
__device__ __forceinline__ int bucket_of(float conf) {
    int bi = (int)(conf * 4096.0f);
    bi = bi < 0 ? 0 : (bi > 4095 ? 4095 : bi);
    return 4095 - bi;                                     // higher conf -> smaller bucket
}
__device__ __forceinline__ unsigned long long make_key(float conf, int idx) {
    unsigned int kh = ~ford(conf);                        // ascending kh == descending conf
    return ((unsigned long long)kh << 32)
         | ((unsigned long long)(unsigned int)idx << 12)
         | (unsigned long long)bucket_of(conf);
}

// ----------------------------------------------------------------------------
// K1: greedy matching per batch + TP-key emission (identical to R15).
//   Proposals bucket-sorted by start (64-bin counting sort in SMEM) so each
//   warp's lanes are spatially adjacent -> warp-uniform gt window (~13/50).
// Dynamic SMEM: pot[2*GG*NW] ints (50,000B) | sxy[NN] float2 (32,000B)
//               | sn[NN] ushort (8,000B)  => 90,000B
// ----------------------------------------------------------------------------
__global__ void __launch_bounds__(512) k_greedy(const float2* __restrict__ segs,
                                                const float2* __restrict__ gts,
                                                const float*  __restrict__ scores) {
    const int b = blockIdx.x, tid = threadIdx.x;
    const int lane = tid & 31, warp = tid >> 5;           // 16 warps
    extern __shared__ unsigned int pot[];                 // [2][GG][NW]
    float2*         sxy = (float2*)(pot + 2 * GG * NW);   // byte 50,000 (8-aligned)
    unsigned short* sn  = (unsigned short*)(sxy + NN);    // byte 82,000
    __shared__ float4 sgt[GG];                            // sorted: {x, y, len, idx-bits}
    __shared__ float2 raw[GG];
    __shared__ unsigned int suse[2][NW];
    __shared__ int s_tab[64];
    __shared__ int s_maxlen;                              // float bits (positive)
    __shared__ int s_cnt[2], s_base[2];
    __shared__ int s_cnt64[64], s_off64[64], s_fill64[64];

    // zero bitmaps + zero this launch's g_c slice (distributed over 256 blocks)
    for (int i = tid; i < 2 * GG * NW; i += 512) pot[i] = 0u;
    for (int i = b * 512 + tid; i < 2 * (TMAX + 1); i += BB * 512) ((int*)g_c)[i] = 0;
    if (tid == 0) s_maxlen = 0;
    if (tid < 2) s_cnt[tid] = 0;
    if (tid < 64) { s_cnt64[tid] = 0; s_fill64[tid] = 0; }
    if (tid < GG) raw[tid] = gts[b * GG + tid];
    __syncthreads();

    // sort gts by start (rank sort, stable on ties) + max length
    if (tid < GG) {
        float2 t = raw[tid];
        int r = 0;
        for (int j = 0; j < GG; ++j) {
            float xj = raw[j].x;
            r += (xj < t.x) || (xj == t.x && j < tid);
        }
        sgt[r] = make_float4(t.x, t.y, t.y - t.x, __int_as_float(tid));
        atomicMax(&s_maxlen, __float_as_int(t.y - t.x)); // positive floats: int cmp ok
    }

    // counting-sort pass A: bin counts of proposal starts (64 bins over [0,1))
    for (int n = tid; n < NN; n += 512) {
        float sx = segs[b * NN + n].x;
        int bq = (int)(sx * 64.0f);
        bq = bq < 0 ? 0 : (bq > 63 ? 63 : bq);
        atomicAdd(&s_cnt64[bq], 1);
    }
    __syncthreads();

    // 64-entry gt start table + 64-bin exclusive scan (warp 0)
    if (tid < 64) {
        float thr = (float)tid * (1.0f / 64.0f);
        int j = 0;
        while (j < GG && sgt[j].x < thr) ++j;
        s_tab[tid] = j;
    }
    if (warp == 0) {
        int c0 = s_cnt64[lane * 2], c1 = s_cnt64[lane * 2 + 1];
        int s2 = c0 + c1, v = s2;
#pragma unroll
        for (int d = 1; d < 32; d <<= 1) {
            int o = __shfl_up_sync(0xFFFFFFFFu, v, d);
            if (lane >= d) v += o;
        }
        int excl = v - s2;
        s_off64[lane * 2] = excl;
        s_off64[lane * 2 + 1] = excl + c0;
    }
    __syncthreads();
    const float maxlg = __int_as_float(s_maxlen);

    // counting-sort pass B: scatter proposals into start-sorted order
    for (int n = tid; n < NN; n += 512) {
        float2 s = segs[b * NN + n];
        int bq = (int)(s.x * 64.0f);
        bq = bq < 0 ? 0 : (bq > 63 ? 63 : bq);
        int pos = s_off64[bq] + atomicAdd(&s_fill64[bq], 1);
        sxy[pos] = s;
        sn[pos] = (unsigned short)n;
    }
    __syncthreads();

    // ---- candidate evaluation: warp-uniform gt window over sorted chunks ----
    for (int ch = warp; ch < NW; ch += 16) {              // 125 chunks of 32
        int i = ch * 32 + lane;                           // always < 4000
        float2 s = sxy[i];
        int n = sn[i];
        float la = s.y - s.x;
        int wn = n >> 5;
        unsigned int bitn = 1u << (n & 31);

        float xlo = s.x - maxlg;
        int q = (int)(xlo * 64.0f) - 1;                   // -1: conservative vs fp round-up
        q = q < 0 ? 0 : (q > 63 ? 63 : q);
        int j0 = s_tab[q];
        int jmin = __reduce_min_sync(0xFFFFFFFFu, j0);
        int symax_i = __reduce_max_sync(0xFFFFFFFFu, __float_as_int(s.y)); // s.y > 0
        float symax = __int_as_float(symax_i);

        for (int j = jmin; j < GG; ++j) {
            float4 t = sgt[j];                            // uniform broadcast LDS.128
            if (t.x >= symax) break;                      // uniform exit: inter<=0 for all
            float inter = fminf(s.y, t.y) - fmaxf(s.x, t.x);
            float ssum  = la + t.z;                       // la + lg (> 0)
            int g = __float_as_int(t.w);
            // iou > 0.5 <=> 3*inter > la+lg ; iou > 0.75 <=> 7*inter > 3*(la+lg)
            if (3.0f * inter > ssum)         atomicOr(&pot[g * NW + wn], bitn);
            if (7.0f * inter > 3.0f * ssum)  atomicOr(&pot[(GG + g) * NW + wn], bitn);
        }
    }
    __syncthreads();

    // ---- greedy claims: one warp per threshold, used bits in registers ----
    if (warp < 2) {
        const int z = warp;
        unsigned int usedreg[4] = {0u, 0u, 0u, 0u};
        const unsigned int* P = pot + z * GG * NW;
        for (int g = 0; g < GG; ++g) {
            unsigned int best = 0xFFFFFFFFu;
#pragma unroll
            for (int s = 0; s < 4; ++s) {
                int w = s * 32 + lane;
                if (w < NW) {
                    unsigned int c = P[g * NW + w] & ~usedreg[s];
                    if (c) best = min(best, (unsigned int)(w * 32 + __ffs(c) - 1));
                }
            }
            unsigned int m = __reduce_min_sync(0xFFFFFFFFu, best);
            if (m != 0xFFFFFFFFu) {
                int wm = (int)(m >> 5);
                if ((wm & 31) == lane) usedreg[wm >> 5] |= 1u << (m & 31);
            }
        }
#pragma unroll
        for (int s = 0; s < 4; ++s) {
            int w = s * 32 + lane;
            if (w < NW) suse[z][w] = usedreg[s];
        }
    }
    __syncthreads();

    // ---- emit TP keys: block-aggregated reservation (1 global atomic per z) --
    int z = -1, w = 0, cnt = 0, lbase = 0;
    unsigned int word = 0;
    if (tid < 2 * NW) {
        z = tid / NW; w = tid % NW;
        word = suse[z][w];
        cnt = __popc(word);
        if (cnt) lbase = atomicAdd(&s_cnt[z], cnt);       // smem offsets
    }
    __syncthreads();
    if (tid < 2) s_base[tid] = s_cnt[tid] ? atomicAdd(&g_T[tid], s_cnt[tid]) : 0;
    __syncthreads();
    if (cnt) {
        int p = s_base[z] + lbase;
        while (word) {
            int bit = __ffs(word) - 1;
            word &= word - 1;
            int idx = b * NN + w * 32 + bit;
            unsigned long long key = make_key(scores[idx], idx);
            g_list[z][p++] = key;
            atomicAdd(&g_bcount[z][(int)(key & 0xFFFull)], 1);
        }
    }
}

// ----------------------------------------------------------------------------
// K2 (fused sort): logic identical to R15, but the grid is PADDED to 148
// blocks (blocks >= 2 exit immediately) to escape the low-grid SM-issue
// throttle (pSmIssueThrottleCtrl vanishes @grid>=148 per B300 microarch).
// SMEM layout (ints): off[0..NBKT] | pad to 16B | fill[NBKT] | skeys (8B-aligned)
// ----------------------------------------------------------------------------
__global__ void __launch_bounds__(1024) k_sort() {
    if (blockIdx.x >= 2) return;                          // grid padding only
    const int z = blockIdx.x, tid = threadIdx.x;
    const int lane = tid & 31, warp = tid >> 5;
    extern __shared__ int ssort[];
    int* off  = ssort;                                    // NBKT+1 ints
    int* fill = ssort + NBKT + 4;                         // byte 16400 = 16-aligned
    unsigned long long* skeys = (unsigned long long*)(ssort + 2 * NBKT + 4); // 8-aligned
    __shared__ int wtot[32];

    int T = g_T[z];

    // load 4 consecutive bucket counts (g_bcount 16-aligned), restore to zero
    int4* bc = (int4*)&g_bcount[z][0];
    int4 c4 = bc[tid];
    bc[tid] = make_int4(0, 0, 0, 0);
    ((int4*)fill)[tid] = make_int4(0, 0, 0, 0);

    // block-wide exclusive scan over 4096 bins (4 per thread)
    int loc[4]; int s = 0;
    loc[0] = s; s += c4.x; loc[1] = s; s += c4.y;
    loc[2] = s; s += c4.z; loc[3] = s; s += c4.w;
    int v = s;
#pragma unroll
    for (int d = 1; d < 32; d <<= 1) {
        int o = __shfl_up_sync(0xFFFFFFFFu, v, d);
        if (lane >= d) v += o;
    }
    if (lane == 31) wtot[warp] = v;
    __syncthreads();
    if (warp == 0) {
        int w = wtot[lane], wi = w;
#pragma unroll
        for (int d = 1; d < 32; d <<= 1) {
            int o = __shfl_up_sync(0xFFFFFFFFu, wi, d);
            if (lane >= d) wi += o;
        }
        wtot[lane] = wi - w;
    }
    __syncthreads();
    int excl = wtot[warp] + (v - s);
    int base = tid * 4;
#pragma unroll
    for (int j = 0; j < 4; ++j) off[base + j] = excl + loc[j];
    if (tid == 1023) off[NBKT] = excl + s;
    __syncthreads();

    // single global pass: keys -> registers -> smem scatter
    for (int i = tid; i < T; i += 1024) {
        unsigned long long k = g_list[z][i];
        int bk = (int)(k & 0xFFFull);
        skeys[off[bk] + atomicAdd(&fill[bk], 1)] = k;
    }
    __syncthreads();

    // thread-per-bucket rank sort (avg ~3 keys/bucket)
    for (int bk = tid; bk < NBKT; bk += 1024) {
        int st = off[bk], en = off[bk + 1];
        for (int i = st; i < en; ++i) {
            unsigned long long k = skeys[i];
            int r = 0;
            for (int j = st; j < en; ++j) r += (skeys[j] < k) ? 1 : 0;
            g_sorted[z][st + r] = k;
        }
    }

    for (int i = tid; i <= NBKT; i += 1024) g_boff[z][i] = off[i];
}

// ----------------------------------------------------------------------------
// K3: lower-bound histogram (identical to R15). 4096-way bucket narrows the
// search to ~3 keys. In-bucket lower bound == global lower bound.
// ----------------------------------------------------------------------------
__global__ void __launch_bounds__(1024) k_hist(const float* __restrict__ scores) {
    const int z = blockIdx.y;
    extern __shared__ int sh[];
    int* soff = sh;                                       // NBKT+1
    unsigned long long* sk = (unsigned long long*)(sh + NBKT + 2); // 8-aligned
    int T = g_T[z];
    for (int i = threadIdx.x; i < T; i += 1024) sk[i] = g_sorted[z][i];
    for (int i = threadIdx.x; i <= NBKT; i += 1024) soff[i] = g_boff[z][i];
    __syncthreads();

    int stride = gridDim.x * 1024;
    for (int idx = blockIdx.x * 1024 + threadIdx.x; idx < M_TOT; idx += stride) {
        unsigned long long key = make_key(__ldg(&scores[idx]), idx);
        int bk = (int)(key & 0xFFFull);
        int lo = soff[bk], hi = soff[bk + 1];
        while (lo < hi) {
            int mid = (lo + hi) >> 1;
            if (sk[mid] < key) lo = mid + 1; else hi = mid;
        }
        atomicAdd(&g_c[z][lo], 1);
    }
}

// ----------------------------------------------------------------------------
// K4: finalize AP per threshold. Logic identical to R15, grid PADDED to 148
// blocks (blocks >= 2 exit immediately) to escape the low-grid issue throttle.
// ----------------------------------------------------------------------------
__global__ void __launch_bounds__(1024) k_final(float* __restrict__ out) {
    if (blockIdx.x >= 2) return;                          // grid padding only
    const int z = blockIdx.x, tid = threadIdx.x;
    const int lane = tid & 31, warp = tid >> 5;
    __shared__ int    wsum[32];
    __shared__ float  wmax[32];
    __shared__ double wdbl[32];
    __shared__ float  s_suf[1024];
    __shared__ float  s_gmax;
    extern __shared__ int sfin[];
    int*   s_c  = sfin;                                   // TMAX+1 (+pad)
    float* prec = (float*)(sfin + TMAX + 4);              // TMAX

    int T = g_T[z];
    if (T == 0) { if (tid == 0) { out[z] = 0.0f; g_T[z] = 0; } return; }
    int bins = T + 1;

    // coalesced stage of the histogram
    for (int i = tid; i < bins; i += 1024) s_c[i] = g_c[z][i];
    __syncthreads();

    int CH = (bins + 1023) >> 10;
    int st = min(tid * CH, bins), en = min(st + CH, bins);

    // ---- block-wide exclusive prefix sum of per-thread bin sums ----
    int ssum = 0;
    for (int p = st; p < en; ++p) ssum += s_c[p];
    int v = ssum;
#pragma unroll
    for (int d = 1; d < 32; d <<= 1) {
        int o = __shfl_up_sync(0xFFFFFFFFu, v, d);
        if (lane >= d) v += o;
    }
    if (lane == 31) wsum[warp] = v;
    __syncthreads();
    if (warp == 0) {
        int w = wsum[lane], wi = w;
#pragma unroll
        for (int d = 1; d < 32; d <<= 1) {
            int o = __shfl_up_sync(0xFFFFFFFFu, wi, d);
            if (lane >= d) wi += o;
        }
        wsum[lane] = wi - w;
    }
    __syncthreads();
    int C = wsum[warp] + (v - ssum);

    // ---- precision values + chunk max ----
    float mx = 0.0f;
    for (int p = st; p < en; ++p) {
        C += s_c[p];
        if (p < T) {
            float pr = (float)(p + 1) / (float)C;
            prec[p] = pr;
            mx = fmaxf(mx, pr);
        }
    }

    // ---- exclusive suffix-max over chunks (reversed exclusive max-scan) ----
    s_suf[1023 - tid] = mx;
    __syncthreads();
    float a = s_suf[tid], ai = a;
#pragma unroll
    for (int d = 1; d < 32; d <<= 1) {
        float o = __shfl_up_sync(0xFFFFFFFFu, ai, d);
        if (lane >= d) ai = fmaxf(ai, o);
    }
    float le = __shfl_up_sync(0xFFFFFFFFu, ai, 1);
    if (lane == 0) le = 0.0f;
    if (lane == 31) wmax[warp] = ai;
    __syncthreads();
    if (warp == 0) {
        float w0 = wmax[lane], wi = w0;
#pragma unroll
        for (int d = 1; d < 32; d <<= 1) {
            float o = __shfl_up_sync(0xFFFFFFFFu, wi, d);
            if (lane >= d) wi = fmaxf(wi, o);
        }
        float e = __shfl_up_sync(0xFFFFFFFFu, wi, 1);
        if (lane == 0) e = 0.0f;
        wmax[lane] = e;
        if (lane == 31) s_gmax = wi;                      // global max precision
    }
    __syncthreads();
    float suf_excl = fmaxf(wmax[warp], le);
    s_suf[tid] = suf_excl;
    __syncthreads();
    float run = s_suf[1023 - tid];
    __syncthreads();

    // ---- weighted sum (descending within chunk, running suffix max) ----
    double s = 0.0;
    int hi = min(en, T);
    for (int p = hi - 1; p >= st; --p) {
        run = fmaxf(run, prec[p]);
        s += (double)run;
    }

    // ---- double reduction ----
#pragma unroll
    for (int d = 16; d; d >>= 1) s += __shfl_down_sync(0xFFFFFFFFu, s, d);
    if (lane == 0) wdbl[warp] = s;
    __syncthreads();
    if (warp == 0) {
        double t = wdbl[lane];
#pragma unroll
        for (int d = 16; d; d >>= 1) t += __shfl_down_sync(0xFFFFFFFFu, t, d);
        if (lane == 0) {
            if (s_c[0] == 1) t -= (double)s_gmax;         // rank-0 TP excluded
            out[z] = (float)(t / (double)(BB * GG));
            g_T[z] = 0;                                   // restore invariant for replay
        }
    }
}

// ----------------------------------------------------------------------------
// Launcher (graph-capturable: kernels only, default stream)
// ----------------------------------------------------------------------------
extern "C" void kernel_launch(void* const* d_in, const int* in_sizes, int n_in,
                              void* d_out, int out_size) {
    const float*  scores = (const float*)d_in[0];
    const float2* segs   = (const float2*)d_in[1];
    const float2* gts    = (const float2*)d_in[2];
    float* out = (float*)d_out;

    const int smem_greedy = 2 * GG * NW * 4 + NN * 8 + NN * 2;     //  90,000 B
    const int smem_sort   = (2 * NBKT + 4) * 4 + TMAX * 8;         // 135,184 B
    const int smem_hist   = (NBKT + 2) * 4 + TMAX * 8;             // 118,792 B
    const int smem_final  = (TMAX + 4 + TMAX) * 4;                 // 102,416 B

    cudaFuncSetAttribute(k_greedy, cudaFuncAttributeMaxDynamicSharedMemorySize, smem_greedy);
    cudaFuncSetAttribute(k_sort,   cudaFuncAttributeMaxDynamicSharedMemorySize, smem_sort);
    cudaFuncSetAttribute(k_hist,   cudaFuncAttributeMaxDynamicSharedMemorySize, smem_hist);
    cudaFuncSetAttribute(k_final,  cudaFuncAttributeMaxDynamicSharedMemorySize, smem_final);

    // Pin all kernels to the same (max) L1/SMEM carveout so consecutive graph
    // nodes never trigger a per-SM carveout repartition between launches.
    cudaFuncSetAttribute(k_greedy, cudaFuncAttributePreferredSharedMemoryCarveout,
                         cudaSharedmemCarveoutMaxShared);
    cudaFuncSetAttribute(k_sort,   cudaFuncAttributePreferredSharedMemoryCarveout,
                         cudaSharedmemCarveoutMaxShared);
    cudaFuncSetAttribute(k_hist,   cudaFuncAttributePreferredSharedMemoryCarveout,
                         cudaSharedmemCarveoutMaxShared);
    cudaFuncSetAttribute(k_final,  cudaFuncAttributePreferredSharedMemoryCarveout,
                         cudaSharedmemCarveoutMaxShared);

    k_greedy<<<BB, 512, smem_greedy>>>(segs, gts, scores);
    k_sort<<<148, 1024, smem_sort>>>();                   // grid padded: blocks >= 2 exit
    k_hist<<<dim3(148, 2), 1024, smem_hist>>>(scores);
    k_final<<<148, 1024, smem_final>>>(out);              // grid padded: blocks >= 2 exit
}